// round 11
// baseline (speedup 1.0000x reference)
#include <cuda_runtime.h>
#include <cstdint>
#include <cstddef>

#define EPSF 1e-5f

typedef unsigned long long u64;

// ------------------------- packed f32x2 helpers -------------------------
__device__ __forceinline__ u64 pk(float lo, float hi) {
    u64 r; asm("mov.b64 %0, {%1, %2};" : "=l"(r) : "f"(lo), "f"(hi)); return r;
}
__device__ __forceinline__ u64 dupf(float v) { return pk(v, v); }
__device__ __forceinline__ u64 fma2(u64 a, u64 b, u64 c) {
    u64 d; asm("fma.rn.f32x2 %0, %1, %2, %3;" : "=l"(d) : "l"(a), "l"(b), "l"(c)); return d;
}
__device__ __forceinline__ void upk(u64 v, float& lo, float& hi) {
    asm("mov.b64 {%0, %1}, %2;" : "=f"(lo), "=f"(hi) : "l"(v));
}

// ------------------------- cp.async helpers ------------------------------
__device__ __forceinline__ uint32_t smem_u32(const void* p) {
    uint32_t a;
    asm("{ .reg .u64 t; cvta.to.shared.u64 t, %1; cvt.u32.u64 %0, t; }" : "=r"(a) : "l"(p));
    return a;
}
__device__ __forceinline__ void cp_async16(uint32_t dst, const void* src) {
    asm volatile("cp.async.cg.shared.global [%0], [%1], 16;" :: "r"(dst), "l"(src) : "memory");
}
#define CP_COMMIT() asm volatile("cp.async.commit_group;" ::: "memory")
#define CP_WAIT0()  asm volatile("cp.async.wait_group 0;" ::: "memory")

// ------------------------- scratch (static device) ----------------------
__device__ float g_Wbig1[384 * 768];   // [c][j]: j<256 -> q1, j>=256 -> k1|v1 (LN w folded)
__device__ float g_Wbig2[256 * 768];
__device__ float g_Wscf[384 * 256];    // [c][o] = Wsc[o][c] * bn_g[o]*rsqrt(var)
__device__ float g_colsum1[768], g_bb1[768];
__device__ float g_colsum2[768], g_bb2[768];
__device__ float g_btot[256];
__device__ float g_buf1[(size_t)32768 * 768];  // [s][0:256]=q1, [256:512]=k1, [512:768]=v1
__device__ float g_buf2[(size_t)32768 * 768];
__device__ float g_o1r[(size_t)32768 * 256];
__device__ float g_o1c[(size_t)32768 * 256];
__device__ float g_o2r[(size_t)32768 * 256];
__device__ float g_o2c[(size_t)32768 * 256];

// ------------------------- 1) fold LN/BN into weights --------------------
__global__ void fold_w_kernel(const float* __restrict__ Wq1, const float* __restrict__ Wkv1,
                              const float* __restrict__ ln1q_w, const float* __restrict__ ln1kv_w,
                              const float* __restrict__ Wq2, const float* __restrict__ Wkv2,
                              const float* __restrict__ ln2q_w, const float* __restrict__ ln2kv_w,
                              const float* __restrict__ Wsc, const float* __restrict__ bn_gamma,
                              const float* __restrict__ bn_var) {
    int idx = blockIdx.x * 256 + threadIdx.x;
    if (idx < 384 * 768) {
        int c = idx / 768, j = idx % 768;
        g_Wbig1[idx] = (j < 256) ? ln1q_w[c] * Wq1[c * 256 + j]
                                 : ln1kv_w[c] * Wkv1[c * 512 + (j - 256)];
    }
    if (idx < 256 * 768) {
        int c = idx / 768, j = idx % 768;
        g_Wbig2[idx] = (j < 256) ? ln2q_w[c] * Wq2[c * 256 + j]
                                 : ln2kv_w[c] * Wkv2[c * 512 + (j - 256)];
    }
    if (idx < 384 * 256) {
        int c = idx / 256, o = idx % 256;
        float g = bn_gamma[o] * rsqrtf(bn_var[o] + EPSF);
        g_Wscf[idx] = Wsc[o * 384 + c] * g;
    }
}

__global__ __launch_bounds__(128)
void fold_cols_kernel(const float* __restrict__ Wq1, const float* __restrict__ Wkv1,
                      const float* __restrict__ ln1q_b, const float* __restrict__ ln1kv_b,
                      const float* __restrict__ Wq2, const float* __restrict__ Wkv2,
                      const float* __restrict__ ln2q_b, const float* __restrict__ ln2kv_b,
                      const float* __restrict__ bout1, const float* __restrict__ bout2,
                      const float* __restrict__ bn_gamma, const float* __restrict__ bn_beta,
                      const float* __restrict__ bn_mean, const float* __restrict__ bn_var) {
    int j = blockIdx.x;
    int t = threadIdx.x;
    float cs1 = 0.f, b1 = 0.f;
    for (int c = t; c < 384; c += 128) {
        cs1 += g_Wbig1[c * 768 + j];
        b1  += (j < 256) ? ln1q_b[c] * Wq1[c * 256 + j]
                         : ln1kv_b[c] * Wkv1[c * 512 + (j - 256)];
    }
    float cs2 = 0.f, b2 = 0.f;
    for (int c = t; c < 256; c += 128) {
        cs2 += g_Wbig2[c * 768 + j];
        b2  += (j < 256) ? ln2q_b[c] * Wq2[c * 256 + j]
                         : ln2kv_b[c] * Wkv2[c * 512 + (j - 256)];
    }
    __shared__ float red[4][128];
    red[0][t] = cs1; red[1][t] = b1; red[2][t] = cs2; red[3][t] = b2;
    __syncthreads();
#pragma unroll
    for (int s = 64; s > 0; s >>= 1) {
        if (t < s) {
#pragma unroll
            for (int v = 0; v < 4; v++) red[v][t] += red[v][t + s];
        }
        __syncthreads();
    }
    if (t == 0) {
        g_colsum1[j] = red[0][0];
        g_bb1[j]     = red[1][0];
        g_colsum2[j] = red[2][0];
        g_bb2[j]     = red[3][0];
        if (j < 256) {
            float g = bn_gamma[j] * rsqrtf(bn_var[j] + EPSF);
            g_btot[j] = (bn_beta[j] - bn_mean[j] * g) + bout1[j] + bout2[j];
        }
    }
}

// ------------------------- f32x2 micro-MMA over 16-deep K-chunk ----------
// A stored NATURAL (float); dup to (v,v) pairs in-register (alu pipe).
// Per kt: A 2x LDS.128 + B 2x LDS.128 (16 wavefronts vs 24 with dup'd-A).
__device__ __forceinline__ void mma16(const float (*As)[132], const float (*Bs)[128],
                                      u64 (&acc)[8][4], int tx, int ty) {
#pragma unroll
    for (int kt = 0; kt < 16; kt++) {
        const ulonglong2* bq = (const ulonglong2*)&Bs[kt][tx * 8];
        ulonglong2 bq0 = bq[0], bq1 = bq[1];
        u64 b0 = bq0.x, b1 = bq0.y, b2 = bq1.x, b3 = bq1.y;
        float4 a0 = *(const float4*)&As[kt][ty * 8];
        float4 a1 = *(const float4*)&As[kt][ty * 8 + 4];
        float af[8] = {a0.x, a0.y, a0.z, a0.w, a1.x, a1.y, a1.z, a1.w};
#pragma unroll
        for (int i = 0; i < 8; i++) {
            u64 ad = dupf(af[i]);
            acc[i][0] = fma2(ad, b0, acc[i][0]);
            acc[i][1] = fma2(ad, b1, acc[i][1]);
            acc[i][2] = fma2(ad, b2, acc[i][2]);
            acc[i][3] = fma2(ad, b3, acc[i][3]);
        }
    }
}

// dynamic smem layout: Asf float[2][16][132] @0 (16896 B), Bs float[2][16][128] @16896 (16384 B)
#define ASF_BYTES (2 * 16 * 132 * 4)
#define BS_OFF    ASF_BYTES
#define SMEM_GEMM_BYTES (ASF_BYTES + 2 * 16 * 128 * 4)

// ------------------------- 2) projection GEMM (pipelined + fused LN stats)
template<int WHICH>
__global__ __launch_bounds__(256, 2)
void proj_gemm_kernel(const float* __restrict__ x) {
    constexpr int K = (WHICH == 0) ? 384 : 256;
    const float* __restrict__ Wf     = (WHICH == 0) ? g_Wbig1   : g_Wbig2;
    const float* __restrict__ colsum = (WHICH == 0) ? g_colsum1 : g_colsum2;
    const float* __restrict__ bb     = (WHICH == 0) ? g_bb1     : g_bb2;
    float* __restrict__ out          = (WHICH == 0) ? g_buf1    : g_buf2;

    extern __shared__ char smem[];
    float (*Asf)[16][132] = (float(*)[16][132])smem;
    float (*Bs)[16][128] = (float(*)[16][128])(smem + BS_OFF);
    const uint32_t sbase = smem_u32(smem);

    const int tid = threadIdx.x;
    const int tx = tid & 15, ty = tid >> 4;
    const int s0 = blockIdx.y * 128;
    const int j0 = blockIdx.x * 128;
    const int b = s0 >> 12, p0 = s0 & 4095;
    const float* xb = x + ((size_t)b * K) * 4096 + p0;

    // staging indices: lin in [0,512): k = lin>>5, f4 = lin&31 (16B granules)
    const int k0 = tid >> 5, f40 = tid & 31;
    const int k1 = k0 + 8, f41 = f40;

    u64 acc[8][4];
#pragma unroll
    for (int i = 0; i < 8; i++)
#pragma unroll
        for (int j = 0; j < 4; j++) acc[i][j] = 0ULL;

    // fused LN stats accumulators (4 spatial cols per thread)
    float asum[4] = {0.f, 0.f, 0.f, 0.f};
    float asq[4]  = {0.f, 0.f, 0.f, 0.f};

    float4 pa0, pa1;
    // prologue: chunk 0
    pa0 = *(const float4*)(xb + (size_t)k0 * 4096 + f40 * 4);
    pa1 = *(const float4*)(xb + (size_t)k1 * 4096 + f41 * 4);
    cp_async16(sbase + BS_OFF + (k0 * 128 + f40 * 4) * 4, Wf + (size_t)k0 * 768 + j0 + f40 * 4);
    cp_async16(sbase + BS_OFF + (k1 * 128 + f41 * 4) * 4, Wf + (size_t)k1 * 768 + j0 + f41 * 4);
    CP_COMMIT();
    asum[0] += pa0.x + pa1.x; asq[0] += pa0.x * pa0.x + pa1.x * pa1.x;
    asum[1] += pa0.y + pa1.y; asq[1] += pa0.y * pa0.y + pa1.y * pa1.y;
    asum[2] += pa0.z + pa1.z; asq[2] += pa0.z * pa0.z + pa1.z * pa1.z;
    asum[3] += pa0.w + pa1.w; asq[3] += pa0.w * pa0.w + pa1.w * pa1.w;
    *(float4*)&Asf[0][k0][f40 * 4] = pa0;
    *(float4*)&Asf[0][k1][f41 * 4] = pa1;

    int buf = 0;
    for (int c0 = 0; c0 < K; c0 += 16, buf ^= 1) {
        CP_WAIT0();
        __syncthreads();
        bool has_next = (c0 + 16 < K);
        if (has_next) {
            const float* xn = xb + (size_t)(c0 + 16) * 4096;
            pa0 = *(const float4*)(xn + (size_t)k0 * 4096 + f40 * 4);
            pa1 = *(const float4*)(xn + (size_t)k1 * 4096 + f41 * 4);
            uint32_t bdst = sbase + BS_OFF + (buf ^ 1) * 8192;
            const float* wn = Wf + (size_t)(c0 + 16) * 768 + j0;
            cp_async16(bdst + (k0 * 128 + f40 * 4) * 4, wn + (size_t)k0 * 768 + f40 * 4);
            cp_async16(bdst + (k1 * 128 + f41 * 4) * 4, wn + (size_t)k1 * 768 + f41 * 4);
            CP_COMMIT();
        }
        mma16(Asf[buf], Bs[buf], acc, tx, ty);
        if (has_next) {
            asum[0] += pa0.x + pa1.x; asq[0] += pa0.x * pa0.x + pa1.x * pa1.x;
            asum[1] += pa0.y + pa1.y; asq[1] += pa0.y * pa0.y + pa1.y * pa1.y;
            asum[2] += pa0.z + pa1.z; asq[2] += pa0.z * pa0.z + pa1.z * pa1.z;
            asum[3] += pa0.w + pa1.w; asq[3] += pa0.w * pa0.w + pa1.w * pa1.w;
            *(float4*)&Asf[buf ^ 1][k0][f40 * 4] = pa0;
            *(float4*)&Asf[buf ^ 1][k1][f41 * 4] = pa1;
        }
    }

    // ---- cross-thread LN-stat reduction through (now idle) smem ----
    __syncthreads();  // everyone done reading GEMM buffers
    float* ps  = (float*)smem;          // [8][128] partial sums
    float* pq  = ps + 1024;             // [8][128] partial sumsq
    float* muS = pq + 1024;             // [128]
    float* rsS = muS + 128;             // [128]
#pragma unroll
    for (int i = 0; i < 4; i++) {
        ps[k0 * 128 + f40 * 4 + i] = asum[i];
        pq[k0 * 128 + f40 * 4 + i] = asq[i];
    }
    __syncthreads();
    if (tid < 128) {
        float s = 0.f, q = 0.f;
#pragma unroll
        for (int r = 0; r < 8; r++) {
            s += ps[r * 128 + tid];
            q += pq[r * 128 + tid];
        }
        float m = s * (1.0f / K);
        float v = q * (1.0f / K) - m * m;
        muS[tid] = m;
        rsS[tid] = rsqrtf(v + EPSF);
    }
    __syncthreads();

    float cs[8], bv[8];
#pragma unroll
    for (int j = 0; j < 8; j++) {
        cs[j] = colsum[j0 + tx * 8 + j];
        bv[j] = bb[j0 + tx * 8 + j];
    }
#pragma unroll
    for (int i = 0; i < 8; i++) {
        int srow = ty * 8 + i;
        int s = s0 + srow;
        float r = rsS[srow], m = muS[srow];
        float c[8];
#pragma unroll
        for (int jj = 0; jj < 4; jj++) upk(acc[i][jj], c[2 * jj], c[2 * jj + 1]);
        float4 o0, o1;
        o0.x = r * (c[0] - m * cs[0]) + bv[0];
        o0.y = r * (c[1] - m * cs[1]) + bv[1];
        o0.z = r * (c[2] - m * cs[2]) + bv[2];
        o0.w = r * (c[3] - m * cs[3]) + bv[3];
        o1.x = r * (c[4] - m * cs[4]) + bv[4];
        o1.y = r * (c[5] - m * cs[5]) + bv[5];
        o1.z = r * (c[6] - m * cs[6]) + bv[6];
        o1.w = r * (c[7] - m * cs[7]) + bv[7];
        float* op = out + (size_t)s * 768 + j0 + tx * 8;
        *(float4*)op = o0;
        *(float4*)(op + 4) = o1;
    }
}

// ------------------------- 3) axial attention ----------------------------
__global__ __launch_bounds__(64)
void attn_kernel() {
    __shared__ __align__(16) float Ks[64][32];
    __shared__ __align__(16) float Vs[64][32];
    const int t = threadIdx.x;
    const int line = blockIdx.x;
    const int b = blockIdx.y >> 3, n = blockIdx.y & 7;
    const int br = blockIdx.z >> 1, dir = blockIdx.z & 1;

    const float* Qb  = br ? g_buf2 : g_buf1;
    const float* KVb = br ? g_buf1 : g_buf2;
    float* ob = br ? (dir ? g_o2c : g_o2r) : (dir ? g_o1c : g_o1r);

    int s_t = (dir == 0) ? (b * 4096 + t * 64 + line) : (b * 4096 + line * 64 + t);

    const float* qp = Qb  + (size_t)s_t * 768 + n * 32;
    const float* kp = KVb + (size_t)s_t * 768 + 256 + n * 32;
    const float* vp = kp + 256;
#pragma unroll
    for (int d4 = 0; d4 < 8; d4++) {
        *(float4*)&Ks[t][d4 * 4] = *(const float4*)(kp + d4 * 4);
        *(float4*)&Vs[t][d4 * 4] = *(const float4*)(vp + d4 * 4);
    }
    u64 q2[16];
#pragma unroll
    for (int d = 0; d < 16; d++) q2[d] = *(const u64*)(qp + 2 * d);
    __syncthreads();

    float sc[64];
    float smax = -1e30f;
#pragma unroll
    for (int j = 0; j < 64; j++) {
        const u64* k2 = (const u64*)Ks[j];
        u64 a = 0ULL;
#pragma unroll
        for (int d = 0; d < 16; d++) a = fma2(q2[d], k2[d], a);
        float lo, hi; upk(a, lo, hi);
        float v = (lo + hi) * 0.17677669529663687f;
        sc[j] = v;
        smax = fmaxf(smax, v);
    }
    float ssum = 0.f;
#pragma unroll
    for (int j = 0; j < 64; j++) {
        float e = __expf(sc[j] - smax);
        sc[j] = e;
        ssum += e;
    }
    float inv = 1.f / ssum;
    u64 o2[16];
#pragma unroll
    for (int d = 0; d < 16; d++) o2[d] = 0ULL;
#pragma unroll
    for (int j = 0; j < 64; j++) {
        u64 pd = dupf(sc[j]);
        const u64* v2 = (const u64*)Vs[j];
#pragma unroll
        for (int d = 0; d < 16; d++) o2[d] = fma2(pd, v2[d], o2[d]);
    }
    u64 iv = dupf(inv);
    float* op = ob + (size_t)s_t * 256 + n * 32;
#pragma unroll
    for (int d = 0; d < 16; d++) {
        u64 r = fma2(o2[d], iv, 0ULL);
        *(u64*)(op + 2 * d) = r;
    }
}

// ------------------------- 4) final fused GEMM (pipelined) ---------------
__global__ __launch_bounds__(256, 2)
void final_gemm_kernel(const float* __restrict__ x1, const float* __restrict__ x2,
                       const float* __restrict__ Wout1, const float* __restrict__ Wout2,
                       float* __restrict__ out) {
    extern __shared__ char smem[];
    float (*Asf)[16][132] = (float(*)[16][132])smem;
    float (*Bs)[16][128] = (float(*)[16][128])(smem + BS_OFF);
    const uint32_t sbase = smem_u32(smem);

    const int tid = threadIdx.x;
    const int tx = tid & 15, ty = tid >> 4;
    const int s0 = blockIdx.y * 128;
    const int j0 = blockIdx.x * 128;
    const int b = s0 >> 12, p0 = s0 & 4095;

    const int k0 = tid >> 5, f40 = tid & 31;
    const int k1 = k0 + 8, f41 = f40;
    // row-major A staging map (phases B/C)
    const int row0 = tid >> 2, q0 = tid & 3;
    const int row1 = (tid + 256) >> 2, q1 = (tid + 256) & 3;

    u64 acc[8][4];
#pragma unroll
    for (int i = 0; i < 8; i++)
#pragma unroll
        for (int j = 0; j < 4; j++) acc[i][j] = 0ULL;

    int buf = 0;

    // ---------- Phase A: shortcut conv (x1 c-major @ g_Wscf), K = 384 ----
    {
        const float* xb = x1 + ((size_t)b * 384) * 4096 + p0;
        float4 pa0, pa1;
        pa0 = *(const float4*)(xb + (size_t)k0 * 4096 + f40 * 4);
        pa1 = *(const float4*)(xb + (size_t)k1 * 4096 + f41 * 4);
        cp_async16(sbase + BS_OFF + buf * 8192 + (k0 * 128 + f40 * 4) * 4,
                   g_Wscf + (size_t)k0 * 256 + j0 + f40 * 4);
        cp_async16(sbase + BS_OFF + buf * 8192 + (k1 * 128 + f41 * 4) * 4,
                   g_Wscf + (size_t)k1 * 256 + j0 + f41 * 4);
        CP_COMMIT();
        *(float4*)&Asf[buf][k0][f40 * 4] = pa0;
        *(float4*)&Asf[buf][k1][f41 * 4] = pa1;
        for (int c0 = 0; c0 < 384; c0 += 16, buf ^= 1) {
            CP_WAIT0();
            __syncthreads();
            bool has_next = (c0 + 16 < 384);
            if (has_next) {
                const float* xn = xb + (size_t)(c0 + 16) * 4096;
                pa0 = *(const float4*)(xn + (size_t)k0 * 4096 + f40 * 4);
                pa1 = *(const float4*)(xn + (size_t)k1 * 4096 + f41 * 4);
                uint32_t bdst = sbase + BS_OFF + (buf ^ 1) * 8192;
                const float* wn = g_Wscf + (size_t)(c0 + 16) * 256 + j0;
                cp_async16(bdst + (k0 * 128 + f40 * 4) * 4, wn + (size_t)k0 * 256 + f40 * 4);
                cp_async16(bdst + (k1 * 128 + f41 * 4) * 4, wn + (size_t)k1 * 256 + f41 * 4);
                CP_COMMIT();
            }
            mma16(Asf[buf], Bs[buf], acc, tx, ty);
            if (has_next) {
                *(float4*)&Asf[buf ^ 1][k0][f40 * 4] = pa0;
                *(float4*)&Asf[buf ^ 1][k1][f41 * 4] = pa1;
            }
        }
    }

    // ---------- Phases B/C: (o_r + o_c) @ Wout, K = 256 each -------------
#pragma unroll
    for (int ph = 0; ph < 2; ph++) {
        const float* o_r = ph ? g_o2r : g_o1r;
        const float* o_c = ph ? g_o2c : g_o1c;
        const float* W   = ph ? Wout2 : Wout1;

        float4 sa0, sa1;
        {
            float4 a = *(const float4*)(o_r + (size_t)(s0 + row0) * 256 + q0 * 4);
            float4 c = *(const float4*)(o_c + (size_t)(s0 + row0) * 256 + q0 * 4);
            sa0 = make_float4(a.x + c.x, a.y + c.y, a.z + c.z, a.w + c.w);
            a = *(const float4*)(o_r + (size_t)(s0 + row1) * 256 + q1 * 4);
            c = *(const float4*)(o_c + (size_t)(s0 + row1) * 256 + q1 * 4);
            sa1 = make_float4(a.x + c.x, a.y + c.y, a.z + c.z, a.w + c.w);
        }
        __syncthreads();  // previous phase readers done before overwriting buf
        cp_async16(sbase + BS_OFF + buf * 8192 + (k0 * 128 + f40 * 4) * 4,
                   W + (size_t)k0 * 256 + j0 + f40 * 4);
        cp_async16(sbase + BS_OFF + buf * 8192 + (k1 * 128 + f41 * 4) * 4,
                   W + (size_t)k1 * 256 + j0 + f41 * 4);
        CP_COMMIT();
        {
            Asf[buf][q0 * 4 + 0][row0] = sa0.x;
            Asf[buf][q0 * 4 + 1][row0] = sa0.y;
            Asf[buf][q0 * 4 + 2][row0] = sa0.z;
            Asf[buf][q0 * 4 + 3][row0] = sa0.w;
            Asf[buf][q1 * 4 + 0][row1] = sa1.x;
            Asf[buf][q1 * 4 + 1][row1] = sa1.y;
            Asf[buf][q1 * 4 + 2][row1] = sa1.z;
            Asf[buf][q1 * 4 + 3][row1] = sa1.w;
        }
        for (int c0 = 0; c0 < 256; c0 += 16, buf ^= 1) {
            CP_WAIT0();
            __syncthreads();
            bool has_next = (c0 + 16 < 256);
            if (has_next) {
                int cn = c0 + 16;
                float4 a = *(const float4*)(o_r + (size_t)(s0 + row0) * 256 + cn + q0 * 4);
                float4 c = *(const float4*)(o_c + (size_t)(s0 + row0) * 256 + cn + q0 * 4);
                sa0 = make_float4(a.x + c.x, a.y + c.y, a.z + c.z, a.w + c.w);
                a = *(const float4*)(o_r + (size_t)(s0 + row1) * 256 + cn + q1 * 4);
                c = *(const float4*)(o_c + (size_t)(s0 + row1) * 256 + cn + q1 * 4);
                sa1 = make_float4(a.x + c.x, a.y + c.y, a.z + c.z, a.w + c.w);
                uint32_t bdst = sbase + BS_OFF + (buf ^ 1) * 8192;
                const float* wn = W + (size_t)cn * 256 + j0;
                cp_async16(bdst + (k0 * 128 + f40 * 4) * 4, wn + (size_t)k0 * 256 + f40 * 4);
                cp_async16(bdst + (k1 * 128 + f41 * 4) * 4, wn + (size_t)k1 * 256 + f41 * 4);
                CP_COMMIT();
            }
            mma16(Asf[buf], Bs[buf], acc, tx, ty);
            if (has_next) {
                Asf[buf ^ 1][q0 * 4 + 0][row0] = sa0.x;
                Asf[buf ^ 1][q0 * 4 + 1][row0] = sa0.y;
                Asf[buf ^ 1][q0 * 4 + 2][row0] = sa0.z;
                Asf[buf ^ 1][q0 * 4 + 3][row0] = sa0.w;
                Asf[buf ^ 1][q1 * 4 + 0][row1] = sa1.x;
                Asf[buf ^ 1][q1 * 4 + 1][row1] = sa1.y;
                Asf[buf ^ 1][q1 * 4 + 2][row1] = sa1.z;
                Asf[buf ^ 1][q1 * 4 + 3][row1] = sa1.w;
            }
        }
    }

    // epilogue: bias + x2 residual, store NCHW
    float cf[8][8];
#pragma unroll
    for (int i = 0; i < 8; i++)
#pragma unroll
        for (int jj = 0; jj < 4; jj++) upk(acc[i][jj], cf[i][2 * jj], cf[i][2 * jj + 1]);

#pragma unroll
    for (int j = 0; j < 8; j++) {
        int o = j0 + tx * 8 + j;
        size_t base = ((size_t)(b * 256 + o)) * 4096 + p0 + ty * 8;
        float bt = g_btot[o];
        float4 xa  = *(const float4*)(x2 + base);
        float4 xb4 = *(const float4*)(x2 + base + 4);
        float4 r0, r1;
        r0.x = cf[0][j] + bt + xa.x;
        r0.y = cf[1][j] + bt + xa.y;
        r0.z = cf[2][j] + bt + xa.z;
        r0.w = cf[3][j] + bt + xa.w;
        r1.x = cf[4][j] + bt + xb4.x;
        r1.y = cf[5][j] + bt + xb4.y;
        r1.z = cf[6][j] + bt + xb4.z;
        r1.w = cf[7][j] + bt + xb4.w;
        *(float4*)(out + base) = r0;
        *(float4*)(out + base + 4) = r1;
    }
}

// ------------------------- launch ---------------------------------------
extern "C" void kernel_launch(void* const* d_in, const int* in_sizes, int n_in,
                              void* d_out, int out_size) {
    (void)in_sizes; (void)n_in; (void)out_size;
    const float* x1      = (const float*)d_in[0];
    const float* x2      = (const float*)d_in[1];
    const float* ln1q_w  = (const float*)d_in[2];
    const float* ln1q_b  = (const float*)d_in[3];
    const float* ln2kv_w = (const float*)d_in[4];
    const float* ln2kv_b = (const float*)d_in[5];
    const float* Wq1     = (const float*)d_in[6];
    const float* Wkv2    = (const float*)d_in[7];
    const float* Wout1   = (const float*)d_in[8];
    const float* bout1   = (const float*)d_in[9];
    const float* ln2q_w  = (const float*)d_in[10];
    const float* ln2q_b  = (const float*)d_in[11];
    const float* ln1kv_w = (const float*)d_in[12];
    const float* ln1kv_b = (const float*)d_in[13];
    const float* Wq2     = (const float*)d_in[14];
    const float* Wkv1    = (const float*)d_in[15];
    const float* Wout2   = (const float*)d_in[16];
    const float* bout2   = (const float*)d_in[17];
    const float* Wsc     = (const float*)d_in[18];
    const float* bn_g    = (const float*)d_in[19];
    const float* bn_b    = (const float*)d_in[20];
    const float* bn_m    = (const float*)d_in[21];
    const float* bn_v    = (const float*)d_in[22];
    float* out = (float*)d_out;

    cudaFuncSetAttribute(proj_gemm_kernel<0>, cudaFuncAttributeMaxDynamicSharedMemorySize, SMEM_GEMM_BYTES);
    cudaFuncSetAttribute(proj_gemm_kernel<1>, cudaFuncAttributeMaxDynamicSharedMemorySize, SMEM_GEMM_BYTES);
    cudaFuncSetAttribute(final_gemm_kernel,   cudaFuncAttributeMaxDynamicSharedMemorySize, SMEM_GEMM_BYTES);

    fold_w_kernel<<<1152, 256>>>(Wq1, Wkv1, ln1q_w, ln1kv_w,
                                 Wq2, Wkv2, ln2q_w, ln2kv_w,
                                 Wsc, bn_g, bn_v);
    fold_cols_kernel<<<768, 128>>>(Wq1, Wkv1, ln1q_b, ln1kv_b,
                                   Wq2, Wkv2, ln2q_b, ln2kv_b,
                                   bout1, bout2, bn_g, bn_b, bn_m, bn_v);
    proj_gemm_kernel<0><<<dim3(6, 256), 256, SMEM_GEMM_BYTES>>>(x1);
    proj_gemm_kernel<1><<<dim3(6, 256), 256, SMEM_GEMM_BYTES>>>(x2);
    attn_kernel<<<dim3(64, 64, 4), 64>>>();
    final_gemm_kernel<<<dim3(2, 256), 256, SMEM_GEMM_BYTES>>>(x1, x2, Wout1, Wout2, out);
}

// round 12
// speedup vs baseline: 1.4821x; 1.4821x over previous
#include <cuda_runtime.h>
#include <cstdint>
#include <cstddef>

#define EPSF 1e-5f

typedef unsigned long long u64;

// ------------------------- packed f32x2 helpers -------------------------
__device__ __forceinline__ u64 pk(float lo, float hi) {
    u64 r; asm("mov.b64 %0, {%1, %2};" : "=l"(r) : "f"(lo), "f"(hi)); return r;
}
__device__ __forceinline__ u64 dupf(float v) { return pk(v, v); }
__device__ __forceinline__ u64 fma2(u64 a, u64 b, u64 c) {
    u64 d; asm("fma.rn.f32x2 %0, %1, %2, %3;" : "=l"(d) : "l"(a), "l"(b), "l"(c)); return d;
}
__device__ __forceinline__ void upk(u64 v, float& lo, float& hi) {
    asm("mov.b64 {%0, %1}, %2;" : "=f"(lo), "=f"(hi) : "l"(v));
}

// ------------------------- cp.async helpers ------------------------------
__device__ __forceinline__ uint32_t smem_u32(const void* p) {
    uint32_t a;
    asm("{ .reg .u64 t; cvta.to.shared.u64 t, %1; cvt.u32.u64 %0, t; }" : "=r"(a) : "l"(p));
    return a;
}
__device__ __forceinline__ void cp_async16(uint32_t dst, const void* src) {
    asm volatile("cp.async.cg.shared.global [%0], [%1], 16;" :: "r"(dst), "l"(src) : "memory");
}
#define CP_COMMIT() asm volatile("cp.async.commit_group;" ::: "memory")
#define CP_WAIT0()  asm volatile("cp.async.wait_group 0;" ::: "memory")

// ------------------------- scratch (static device) ----------------------
__device__ float g_Wbig1[384 * 768];
__device__ float g_Wbig2[256 * 768];
__device__ float g_Wscf[384 * 256];
__device__ float g_colsum1[768], g_bb1[768];
__device__ float g_colsum2[768], g_bb2[768];
__device__ float g_btot[256];
__device__ float g_buf1[(size_t)32768 * 768];
__device__ float g_buf2[(size_t)32768 * 768];
__device__ float g_o1r[(size_t)32768 * 256];
__device__ float g_o1c[(size_t)32768 * 256];
__device__ float g_o2r[(size_t)32768 * 256];
__device__ float g_o2c[(size_t)32768 * 256];

// ------------------------- 1) fold LN/BN into weights --------------------
__global__ void fold_w_kernel(const float* __restrict__ Wq1, const float* __restrict__ Wkv1,
                              const float* __restrict__ ln1q_w, const float* __restrict__ ln1kv_w,
                              const float* __restrict__ Wq2, const float* __restrict__ Wkv2,
                              const float* __restrict__ ln2q_w, const float* __restrict__ ln2kv_w,
                              const float* __restrict__ Wsc, const float* __restrict__ bn_gamma,
                              const float* __restrict__ bn_var) {
    int idx = blockIdx.x * 256 + threadIdx.x;
    if (idx < 384 * 768) {
        int c = idx / 768, j = idx % 768;
        g_Wbig1[idx] = (j < 256) ? ln1q_w[c] * Wq1[c * 256 + j]
                                 : ln1kv_w[c] * Wkv1[c * 512 + (j - 256)];
    }
    if (idx < 256 * 768) {
        int c = idx / 768, j = idx % 768;
        g_Wbig2[idx] = (j < 256) ? ln2q_w[c] * Wq2[c * 256 + j]
                                 : ln2kv_w[c] * Wkv2[c * 512 + (j - 256)];
    }
    if (idx < 384 * 256) {
        int c = idx / 256, o = idx % 256;
        float g = bn_gamma[o] * rsqrtf(bn_var[o] + EPSF);
        g_Wscf[idx] = Wsc[o * 384 + c] * g;
    }
}

__global__ __launch_bounds__(128)
void fold_cols_kernel(const float* __restrict__ Wq1, const float* __restrict__ Wkv1,
                      const float* __restrict__ ln1q_b, const float* __restrict__ ln1kv_b,
                      const float* __restrict__ Wq2, const float* __restrict__ Wkv2,
                      const float* __restrict__ ln2q_b, const float* __restrict__ ln2kv_b,
                      const float* __restrict__ bout1, const float* __restrict__ bout2,
                      const float* __restrict__ bn_gamma, const float* __restrict__ bn_beta,
                      const float* __restrict__ bn_mean, const float* __restrict__ bn_var) {
    int j = blockIdx.x;
    int t = threadIdx.x;
    float cs1 = 0.f, b1 = 0.f;
    for (int c = t; c < 384; c += 128) {
        cs1 += g_Wbig1[c * 768 + j];
        b1  += (j < 256) ? ln1q_b[c] * Wq1[c * 256 + j]
                         : ln1kv_b[c] * Wkv1[c * 512 + (j - 256)];
    }
    float cs2 = 0.f, b2 = 0.f;
    for (int c = t; c < 256; c += 128) {
        cs2 += g_Wbig2[c * 768 + j];
        b2  += (j < 256) ? ln2q_b[c] * Wq2[c * 256 + j]
                         : ln2kv_b[c] * Wkv2[c * 512 + (j - 256)];
    }
    __shared__ float red[4][128];
    red[0][t] = cs1; red[1][t] = b1; red[2][t] = cs2; red[3][t] = b2;
    __syncthreads();
#pragma unroll
    for (int s = 64; s > 0; s >>= 1) {
        if (t < s) {
#pragma unroll
            for (int v = 0; v < 4; v++) red[v][t] += red[v][t + s];
        }
        __syncthreads();
    }
    if (t == 0) {
        g_colsum1[j] = red[0][0];
        g_bb1[j]     = red[1][0];
        g_colsum2[j] = red[2][0];
        g_bb2[j]     = red[3][0];
        if (j < 256) {
            float g = bn_gamma[j] * rsqrtf(bn_var[j] + EPSF);
            g_btot[j] = (bn_beta[j] - bn_mean[j] * g) + bout1[j] + bout2[j];
        }
    }
}

// ------------------------- f32x2 micro-MMA, 8x16 thread tile -------------
// A dup'd u64 in smem (broadcast within phase); B 16 cols spread as 4x float4
// at 64-col stride (conflict-free phases). 64 FMA2 per kt per thread.
__device__ __forceinline__ void mma16w(const u64 (*As)[130], const float (*Bs)[256],
                                       u64 (&acc)[8][8], int tx, int ty) {
#pragma unroll 4
    for (int kt = 0; kt < 16; kt++) {
        const ulonglong2* aq = (const ulonglong2*)&As[kt][ty * 8];
        ulonglong2 a01 = aq[0], a23 = aq[1], a45 = aq[2], a67 = aq[3];
        u64 a[8] = {a01.x, a01.y, a23.x, a23.y, a45.x, a45.y, a67.x, a67.y};
        u64 b[8];
#pragma unroll
        for (int q = 0; q < 4; q++) {
            ulonglong2 bv = *(const ulonglong2*)&Bs[kt][q * 64 + tx * 4];
            b[q * 2] = bv.x; b[q * 2 + 1] = bv.y;
        }
#pragma unroll
        for (int i = 0; i < 8; i++)
#pragma unroll
            for (int j = 0; j < 8; j++)
                acc[i][j] = fma2(a[i], b[j], acc[i][j]);
    }
}

// dynamic smem: Asd u64[2][16][130] @0 (33280 B), Bs float[2][16][256] @33280 (32768 B)
#define BS_OFF 33280
#define SMEM_GEMM_BYTES (33280 + 32768)

// ------------------------- 2) projection GEMM ----------------------------
template<int WHICH>
__global__ __launch_bounds__(256, 1)
void proj_gemm_kernel(const float* __restrict__ x) {
    constexpr int K = (WHICH == 0) ? 384 : 256;
    const float* __restrict__ Wf     = (WHICH == 0) ? g_Wbig1   : g_Wbig2;
    const float* __restrict__ colsum = (WHICH == 0) ? g_colsum1 : g_colsum2;
    const float* __restrict__ bb     = (WHICH == 0) ? g_bb1     : g_bb2;
    float* __restrict__ out          = (WHICH == 0) ? g_buf1    : g_buf2;

    extern __shared__ char smem[];
    u64 (*Asd)[16][130] = (u64(*)[16][130])smem;
    float (*Bs)[16][256] = (float(*)[16][256])(smem + BS_OFF);
    const uint32_t sbase = smem_u32(smem);

    const int tid = threadIdx.x;
    const int tx = tid & 15, ty = tid >> 4;
    const int s0 = blockIdx.y * 128;
    const int j0 = blockIdx.x * 256;
    const int b = s0 >> 12, p0 = s0 & 4095;
    const float* xb = x + ((size_t)b * K) * 4096 + p0;

    // A staging: k0/k1 rows, f40 16B-granule within 128-float row
    const int k0 = tid >> 5, f40 = tid & 31;
    const int k1 = k0 + 8;
    // B staging: 4 granules per thread over 16x256 tile
    // g = tid + i*256: kB = g>>6, colB16 = g&63 (granule of 4 floats)

    u64 acc[8][8];
#pragma unroll
    for (int i = 0; i < 8; i++)
#pragma unroll
        for (int j = 0; j < 8; j++) acc[i][j] = 0ULL;

    float asum[4] = {0.f, 0.f, 0.f, 0.f};
    float asq[4]  = {0.f, 0.f, 0.f, 0.f};

    float4 pa0, pa1;
    // prologue: chunk 0
    pa0 = *(const float4*)(xb + (size_t)k0 * 4096 + f40 * 4);
    pa1 = *(const float4*)(xb + (size_t)k1 * 4096 + f40 * 4);
#pragma unroll
    for (int i = 0; i < 4; i++) {
        int g = tid + i * 256;
        int kB = g >> 6, cB = g & 63;
        cp_async16(sbase + BS_OFF + kB * 1024 + cB * 16,
                   Wf + (size_t)kB * 768 + j0 + cB * 4);
    }
    CP_COMMIT();
    asum[0] += pa0.x + pa1.x; asq[0] += pa0.x * pa0.x + pa1.x * pa1.x;
    asum[1] += pa0.y + pa1.y; asq[1] += pa0.y * pa0.y + pa1.y * pa1.y;
    asum[2] += pa0.z + pa1.z; asq[2] += pa0.z * pa0.z + pa1.z * pa1.z;
    asum[3] += pa0.w + pa1.w; asq[3] += pa0.w * pa0.w + pa1.w * pa1.w;
    {
        float* d0 = (float*)&Asd[0][k0][f40 * 4];
        *(float4*)d0       = make_float4(pa0.x, pa0.x, pa0.y, pa0.y);
        *(float4*)(d0 + 4) = make_float4(pa0.z, pa0.z, pa0.w, pa0.w);
        float* d1 = (float*)&Asd[0][k1][f40 * 4];
        *(float4*)d1       = make_float4(pa1.x, pa1.x, pa1.y, pa1.y);
        *(float4*)(d1 + 4) = make_float4(pa1.z, pa1.z, pa1.w, pa1.w);
    }

    int buf = 0;
    for (int c0 = 0; c0 < K; c0 += 16, buf ^= 1) {
        CP_WAIT0();
        __syncthreads();
        bool has_next = (c0 + 16 < K);
        if (has_next) {
            const float* xn = xb + (size_t)(c0 + 16) * 4096;
            pa0 = *(const float4*)(xn + (size_t)k0 * 4096 + f40 * 4);
            pa1 = *(const float4*)(xn + (size_t)k1 * 4096 + f40 * 4);
            uint32_t bdst = sbase + BS_OFF + (buf ^ 1) * 16384;
            const float* wn = Wf + (size_t)(c0 + 16) * 768 + j0;
#pragma unroll
            for (int i = 0; i < 4; i++) {
                int g = tid + i * 256;
                int kB = g >> 6, cB = g & 63;
                cp_async16(bdst + kB * 1024 + cB * 16, wn + (size_t)kB * 768 + cB * 4);
            }
            CP_COMMIT();
        }
        mma16w(Asd[buf], Bs[buf], acc, tx, ty);
        if (has_next) {
            asum[0] += pa0.x + pa1.x; asq[0] += pa0.x * pa0.x + pa1.x * pa1.x;
            asum[1] += pa0.y + pa1.y; asq[1] += pa0.y * pa0.y + pa1.y * pa1.y;
            asum[2] += pa0.z + pa1.z; asq[2] += pa0.z * pa0.z + pa1.z * pa1.z;
            asum[3] += pa0.w + pa1.w; asq[3] += pa0.w * pa0.w + pa1.w * pa1.w;
            float* d0 = (float*)&Asd[buf ^ 1][k0][f40 * 4];
            *(float4*)d0       = make_float4(pa0.x, pa0.x, pa0.y, pa0.y);
            *(float4*)(d0 + 4) = make_float4(pa0.z, pa0.z, pa0.w, pa0.w);
            float* d1 = (float*)&Asd[buf ^ 1][k1][f40 * 4];
            *(float4*)d1       = make_float4(pa1.x, pa1.x, pa1.y, pa1.y);
            *(float4*)(d1 + 4) = make_float4(pa1.z, pa1.z, pa1.w, pa1.w);
        }
    }

    // ---- cross-thread LN-stat reduction through (now idle) smem ----
    __syncthreads();
    float* ps  = (float*)smem;          // [8][128]
    float* pq  = ps + 1024;             // [8][128]
    float* muS = pq + 1024;             // [128]
    float* rsS = muS + 128;             // [128]
#pragma unroll
    for (int i = 0; i < 4; i++) {
        ps[k0 * 128 + f40 * 4 + i] = asum[i];
        pq[k0 * 128 + f40 * 4 + i] = asq[i];
    }
    __syncthreads();
    if (tid < 128) {
        float s = 0.f, q = 0.f;
#pragma unroll
        for (int r = 0; r < 8; r++) {
            s += ps[r * 128 + tid];
            q += pq[r * 128 + tid];
        }
        float m = s * (1.0f / K);
        float v = q * (1.0f / K) - m * m;
        muS[tid] = m;
        rsS[tid] = rsqrtf(v + EPSF);
    }
    __syncthreads();

#pragma unroll
    for (int i = 0; i < 8; i++) {
        int srow = ty * 8 + i;
        int s = s0 + srow;
        float r = rsS[srow], m = muS[srow];
#pragma unroll
        for (int q = 0; q < 4; q++) {
            int jb = j0 + q * 64 + tx * 4;
            float4 cs = *(const float4*)(colsum + jb);
            float4 bv = *(const float4*)(bb + jb);
            float c0f, c1f, c2f, c3f;
            upk(acc[i][q * 2],     c0f, c1f);
            upk(acc[i][q * 2 + 1], c2f, c3f);
            float4 o;
            o.x = r * (c0f - m * cs.x) + bv.x;
            o.y = r * (c1f - m * cs.y) + bv.y;
            o.z = r * (c2f - m * cs.z) + bv.z;
            o.w = r * (c3f - m * cs.w) + bv.w;
            *(float4*)(out + (size_t)s * 768 + jb) = o;
        }
    }
}

// ------------------------- 3) axial attention ----------------------------
__global__ __launch_bounds__(64)
void attn_kernel() {
    __shared__ __align__(16) float Ks[64][32];
    __shared__ __align__(16) float Vs[64][32];
    const int t = threadIdx.x;
    const int line = blockIdx.x;
    const int b = blockIdx.y >> 3, n = blockIdx.y & 7;
    const int br = blockIdx.z >> 1, dir = blockIdx.z & 1;

    const float* Qb  = br ? g_buf2 : g_buf1;
    const float* KVb = br ? g_buf1 : g_buf2;
    float* ob = br ? (dir ? g_o2c : g_o2r) : (dir ? g_o1c : g_o1r);

    int s_t = (dir == 0) ? (b * 4096 + t * 64 + line) : (b * 4096 + line * 64 + t);

    const float* qp = Qb  + (size_t)s_t * 768 + n * 32;
    const float* kp = KVb + (size_t)s_t * 768 + 256 + n * 32;
    const float* vp = kp + 256;
#pragma unroll
    for (int d4 = 0; d4 < 8; d4++) {
        *(float4*)&Ks[t][d4 * 4] = *(const float4*)(kp + d4 * 4);
        *(float4*)&Vs[t][d4 * 4] = *(const float4*)(vp + d4 * 4);
    }
    u64 q2[16];
#pragma unroll
    for (int d = 0; d < 16; d++) q2[d] = *(const u64*)(qp + 2 * d);
    __syncthreads();

    float sc[64];
    float smax = -1e30f;
#pragma unroll
    for (int j = 0; j < 64; j++) {
        const u64* k2 = (const u64*)Ks[j];
        u64 a = 0ULL;
#pragma unroll
        for (int d = 0; d < 16; d++) a = fma2(q2[d], k2[d], a);
        float lo, hi; upk(a, lo, hi);
        float v = (lo + hi) * 0.17677669529663687f;
        sc[j] = v;
        smax = fmaxf(smax, v);
    }
    float ssum = 0.f;
#pragma unroll
    for (int j = 0; j < 64; j++) {
        float e = __expf(sc[j] - smax);
        sc[j] = e;
        ssum += e;
    }
    float inv = 1.f / ssum;
    u64 o2[16];
#pragma unroll
    for (int d = 0; d < 16; d++) o2[d] = 0ULL;
#pragma unroll
    for (int j = 0; j < 64; j++) {
        u64 pd = dupf(sc[j]);
        const u64* v2 = (const u64*)Vs[j];
#pragma unroll
        for (int d = 0; d < 16; d++) o2[d] = fma2(pd, v2[d], o2[d]);
    }
    u64 iv = dupf(inv);
    float* op = ob + (size_t)s_t * 256 + n * 32;
#pragma unroll
    for (int d = 0; d < 16; d++) {
        u64 r = fma2(o2[d], iv, 0ULL);
        *(u64*)(op + 2 * d) = r;
    }
}

// ------------------------- 4) final fused GEMM ---------------------------
__global__ __launch_bounds__(256, 1)
void final_gemm_kernel(const float* __restrict__ x1, const float* __restrict__ x2,
                       const float* __restrict__ Wout1, const float* __restrict__ Wout2,
                       float* __restrict__ out) {
    extern __shared__ char smem[];
    u64 (*Asd)[16][130] = (u64(*)[16][130])smem;
    float (*Bs)[16][256] = (float(*)[16][256])(smem + BS_OFF);
    const uint32_t sbase = smem_u32(smem);

    const int tid = threadIdx.x;
    const int tx = tid & 15, ty = tid >> 4;
    const int s0 = blockIdx.x * 128;
    const int b = s0 >> 12, p0 = s0 & 4095;

    const int k0 = tid >> 5, f40 = tid & 31;
    const int k1 = k0 + 8;
    // row-major A staging map (phases B/C)
    const int row0 = tid >> 2, q0 = tid & 3;
    const int row1 = (tid + 256) >> 2, q1 = (tid + 256) & 3;

    u64 acc[8][8];
#pragma unroll
    for (int i = 0; i < 8; i++)
#pragma unroll
        for (int j = 0; j < 8; j++) acc[i][j] = 0ULL;

    int buf = 0;

    // ---------- Phase A: shortcut conv (x1 c-major @ g_Wscf), K = 384 ----
    {
        const float* xb = x1 + ((size_t)b * 384) * 4096 + p0;
        float4 pa0, pa1;
        pa0 = *(const float4*)(xb + (size_t)k0 * 4096 + f40 * 4);
        pa1 = *(const float4*)(xb + (size_t)k1 * 4096 + f40 * 4);
#pragma unroll
        for (int i = 0; i < 4; i++) {
            int g = tid + i * 256;
            int kB = g >> 6, cB = g & 63;
            cp_async16(sbase + BS_OFF + buf * 16384 + kB * 1024 + cB * 16,
                       g_Wscf + (size_t)kB * 256 + cB * 4);
        }
        CP_COMMIT();
        {
            float* d0 = (float*)&Asd[buf][k0][f40 * 4];
            *(float4*)d0       = make_float4(pa0.x, pa0.x, pa0.y, pa0.y);
            *(float4*)(d0 + 4) = make_float4(pa0.z, pa0.z, pa0.w, pa0.w);
            float* d1 = (float*)&Asd[buf][k1][f40 * 4];
            *(float4*)d1       = make_float4(pa1.x, pa1.x, pa1.y, pa1.y);
            *(float4*)(d1 + 4) = make_float4(pa1.z, pa1.z, pa1.w, pa1.w);
        }
        for (int c0 = 0; c0 < 384; c0 += 16, buf ^= 1) {
            CP_WAIT0();
            __syncthreads();
            bool has_next = (c0 + 16 < 384);
            if (has_next) {
                const float* xn = xb + (size_t)(c0 + 16) * 4096;
                pa0 = *(const float4*)(xn + (size_t)k0 * 4096 + f40 * 4);
                pa1 = *(const float4*)(xn + (size_t)k1 * 4096 + f40 * 4);
                uint32_t bdst = sbase + BS_OFF + (buf ^ 1) * 16384;
                const float* wn = g_Wscf + (size_t)(c0 + 16) * 256;
#pragma unroll
                for (int i = 0; i < 4; i++) {
                    int g = tid + i * 256;
                    int kB = g >> 6, cB = g & 63;
                    cp_async16(bdst + kB * 1024 + cB * 16, wn + (size_t)kB * 256 + cB * 4);
                }
                CP_COMMIT();
            }
            mma16w(Asd[buf], Bs[buf], acc, tx, ty);
            if (has_next) {
                float* d0 = (float*)&Asd[buf ^ 1][k0][f40 * 4];
                *(float4*)d0       = make_float4(pa0.x, pa0.x, pa0.y, pa0.y);
                *(float4*)(d0 + 4) = make_float4(pa0.z, pa0.z, pa0.w, pa0.w);
                float* d1 = (float*)&Asd[buf ^ 1][k1][f40 * 4];
                *(float4*)d1       = make_float4(pa1.x, pa1.x, pa1.y, pa1.y);
                *(float4*)(d1 + 4) = make_float4(pa1.z, pa1.z, pa1.w, pa1.w);
            }
        }
    }

    // ---------- Phases B/C: (o_r + o_c) @ Wout, K = 256 each -------------
#pragma unroll
    for (int ph = 0; ph < 2; ph++) {
        const float* o_r = ph ? g_o2r : g_o1r;
        const float* o_c = ph ? g_o2c : g_o1c;
        const float* W   = ph ? Wout2 : Wout1;

        float4 sa0, sa1;
        {
            float4 a = *(const float4*)(o_r + (size_t)(s0 + row0) * 256 + q0 * 4);
            float4 c = *(const float4*)(o_c + (size_t)(s0 + row0) * 256 + q0 * 4);
            sa0 = make_float4(a.x + c.x, a.y + c.y, a.z + c.z, a.w + c.w);
            a = *(const float4*)(o_r + (size_t)(s0 + row1) * 256 + q1 * 4);
            c = *(const float4*)(o_c + (size_t)(s0 + row1) * 256 + q1 * 4);
            sa1 = make_float4(a.x + c.x, a.y + c.y, a.z + c.z, a.w + c.w);
        }
        __syncthreads();  // previous phase readers done before overwriting buf
#pragma unroll
        for (int i = 0; i < 4; i++) {
            int g = tid + i * 256;
            int kB = g >> 6, cB = g & 63;
            cp_async16(sbase + BS_OFF + buf * 16384 + kB * 1024 + cB * 16,
                       W + (size_t)kB * 256 + cB * 4);
        }
        CP_COMMIT();
        {
            Asd[buf][q0 * 4 + 0][row0] = dupf(sa0.x);
            Asd[buf][q0 * 4 + 1][row0] = dupf(sa0.y);
            Asd[buf][q0 * 4 + 2][row0] = dupf(sa0.z);
            Asd[buf][q0 * 4 + 3][row0] = dupf(sa0.w);
            Asd[buf][q1 * 4 + 0][row1] = dupf(sa1.x);
            Asd[buf][q1 * 4 + 1][row1] = dupf(sa1.y);
            Asd[buf][q1 * 4 + 2][row1] = dupf(sa1.z);
            Asd[buf][q1 * 4 + 3][row1] = dupf(sa1.w);
        }
        for (int c0 = 0; c0 < 256; c0 += 16, buf ^= 1) {
            CP_WAIT0();
            __syncthreads();
            bool has_next = (c0 + 16 < 256);
            if (has_next) {
                int cn = c0 + 16;
                float4 a = *(const float4*)(o_r + (size_t)(s0 + row0) * 256 + cn + q0 * 4);
                float4 c = *(const float4*)(o_c + (size_t)(s0 + row0) * 256 + cn + q0 * 4);
                sa0 = make_float4(a.x + c.x, a.y + c.y, a.z + c.z, a.w + c.w);
                a = *(const float4*)(o_r + (size_t)(s0 + row1) * 256 + cn + q1 * 4);
                c = *(const float4*)(o_c + (size_t)(s0 + row1) * 256 + cn + q1 * 4);
                sa1 = make_float4(a.x + c.x, a.y + c.y, a.z + c.z, a.w + c.w);
                uint32_t bdst = sbase + BS_OFF + (buf ^ 1) * 16384;
                const float* wn = W + (size_t)cn * 256;
#pragma unroll
                for (int i = 0; i < 4; i++) {
                    int g = tid + i * 256;
                    int kB = g >> 6, cB = g & 63;
                    cp_async16(bdst + kB * 1024 + cB * 16, wn + (size_t)kB * 256 + cB * 4);
                }
                CP_COMMIT();
            }
            mma16w(Asd[buf], Bs[buf], acc, tx, ty);
            if (has_next) {
                Asd[buf ^ 1][q0 * 4 + 0][row0] = dupf(sa0.x);
                Asd[buf ^ 1][q0 * 4 + 1][row0] = dupf(sa0.y);
                Asd[buf ^ 1][q0 * 4 + 2][row0] = dupf(sa0.z);
                Asd[buf ^ 1][q0 * 4 + 3][row0] = dupf(sa0.w);
                Asd[buf ^ 1][q1 * 4 + 0][row1] = dupf(sa1.x);
                Asd[buf ^ 1][q1 * 4 + 1][row1] = dupf(sa1.y);
                Asd[buf ^ 1][q1 * 4 + 2][row1] = dupf(sa1.z);
                Asd[buf ^ 1][q1 * 4 + 3][row1] = dupf(sa1.w);
            }
        }
    }

    // epilogue: bias + x2 residual, store NCHW (cols = q*64 + tx*4 + c)
    float cf[8][16];
#pragma unroll
    for (int i = 0; i < 8; i++)
#pragma unroll
        for (int j = 0; j < 8; j++)
            upk(acc[i][j], cf[i][2 * j], cf[i][2 * j + 1]);

#pragma unroll
    for (int q = 0; q < 4; q++) {
#pragma unroll
        for (int c = 0; c < 4; c++) {
            int o = q * 64 + tx * 4 + c;
            int l = q * 4 + c;
            size_t base = ((size_t)(b * 256 + o)) * 4096 + p0 + ty * 8;
            float bt = g_btot[o];
            float4 xa  = *(const float4*)(x2 + base);
            float4 xb4 = *(const float4*)(x2 + base + 4);
            float4 r0, r1;
            r0.x = cf[0][l] + bt + xa.x;
            r0.y = cf[1][l] + bt + xa.y;
            r0.z = cf[2][l] + bt + xa.z;
            r0.w = cf[3][l] + bt + xa.w;
            r1.x = cf[4][l] + bt + xb4.x;
            r1.y = cf[5][l] + bt + xb4.y;
            r1.z = cf[6][l] + bt + xb4.z;
            r1.w = cf[7][l] + bt + xb4.w;
            *(float4*)(out + base) = r0;
            *(float4*)(out + base + 4) = r1;
        }
    }
}

// ------------------------- launch ---------------------------------------
extern "C" void kernel_launch(void* const* d_in, const int* in_sizes, int n_in,
                              void* d_out, int out_size) {
    (void)in_sizes; (void)n_in; (void)out_size;
    const float* x1      = (const float*)d_in[0];
    const float* x2      = (const float*)d_in[1];
    const float* ln1q_w  = (const float*)d_in[2];
    const float* ln1q_b  = (const float*)d_in[3];
    const float* ln2kv_w = (const float*)d_in[4];
    const float* ln2kv_b = (const float*)d_in[5];
    const float* Wq1     = (const float*)d_in[6];
    const float* Wkv2    = (const float*)d_in[7];
    const float* Wout1   = (const float*)d_in[8];
    const float* bout1   = (const float*)d_in[9];
    const float* ln2q_w  = (const float*)d_in[10];
    const float* ln2q_b  = (const float*)d_in[11];
    const float* ln1kv_w = (const float*)d_in[12];
    const float* ln1kv_b = (const float*)d_in[13];
    const float* Wq2     = (const float*)d_in[14];
    const float* Wkv1    = (const float*)d_in[15];
    const float* Wout2   = (const float*)d_in[16];
    const float* bout2   = (const float*)d_in[17];
    const float* Wsc     = (const float*)d_in[18];
    const float* bn_g    = (const float*)d_in[19];
    const float* bn_b    = (const float*)d_in[20];
    const float* bn_m    = (const float*)d_in[21];
    const float* bn_v    = (const float*)d_in[22];
    float* out = (float*)d_out;

    cudaFuncSetAttribute(proj_gemm_kernel<0>, cudaFuncAttributeMaxDynamicSharedMemorySize, SMEM_GEMM_BYTES);
    cudaFuncSetAttribute(proj_gemm_kernel<1>, cudaFuncAttributeMaxDynamicSharedMemorySize, SMEM_GEMM_BYTES);
    cudaFuncSetAttribute(final_gemm_kernel,   cudaFuncAttributeMaxDynamicSharedMemorySize, SMEM_GEMM_BYTES);

    fold_w_kernel<<<1152, 256>>>(Wq1, Wkv1, ln1q_w, ln1kv_w,
                                 Wq2, Wkv2, ln2q_w, ln2kv_w,
                                 Wsc, bn_g, bn_v);
    fold_cols_kernel<<<768, 128>>>(Wq1, Wkv1, ln1q_b, ln1kv_b,
                                   Wq2, Wkv2, ln2q_b, ln2kv_b,
                                   bout1, bout2, bn_g, bn_b, bn_m, bn_v);
    proj_gemm_kernel<0><<<dim3(3, 256), 256, SMEM_GEMM_BYTES>>>(x1);
    proj_gemm_kernel<1><<<dim3(3, 256), 256, SMEM_GEMM_BYTES>>>(x2);
    attn_kernel<<<dim3(64, 64, 4), 64>>>();
    final_gemm_kernel<<<256, 256, SMEM_GEMM_BYTES>>>(x1, x2, Wout1, Wout2, out);
}

// round 13
// speedup vs baseline: 1.5898x; 1.0726x over previous
#include <cuda_runtime.h>
#include <cstdint>
#include <cstddef>

#define EPSF 1e-5f

typedef unsigned long long u64;

// ------------------------- packed f32x2 helpers -------------------------
__device__ __forceinline__ u64 pk(float lo, float hi) {
    u64 r; asm("mov.b64 %0, {%1, %2};" : "=l"(r) : "f"(lo), "f"(hi)); return r;
}
__device__ __forceinline__ u64 dupf(float v) { return pk(v, v); }
__device__ __forceinline__ u64 fma2(u64 a, u64 b, u64 c) {
    u64 d; asm("fma.rn.f32x2 %0, %1, %2, %3;" : "=l"(d) : "l"(a), "l"(b), "l"(c)); return d;
}
__device__ __forceinline__ void upk(u64 v, float& lo, float& hi) {
    asm("mov.b64 {%0, %1}, %2;" : "=f"(lo), "=f"(hi) : "l"(v));
}

// ------------------------- cp.async helpers ------------------------------
__device__ __forceinline__ uint32_t smem_u32(const void* p) {
    uint32_t a;
    asm("{ .reg .u64 t; cvta.to.shared.u64 t, %1; cvt.u32.u64 %0, t; }" : "=r"(a) : "l"(p));
    return a;
}
__device__ __forceinline__ void cp_async16(uint32_t dst, const void* src) {
    asm volatile("cp.async.cg.shared.global [%0], [%1], 16;" :: "r"(dst), "l"(src) : "memory");
}
#define CP_COMMIT() asm volatile("cp.async.commit_group;" ::: "memory")
#define CP_WAIT0()  asm volatile("cp.async.wait_group 0;" ::: "memory")

// ------------------------- scratch (static device) ----------------------
__device__ float g_Wbig1[384 * 768];
__device__ float g_Wbig2[256 * 768];
__device__ float g_Wscf[384 * 256];
__device__ float g_colsum1[768], g_bb1[768];
__device__ float g_colsum2[768], g_bb2[768];
__device__ float g_btot[256];
__device__ float g_buf1[(size_t)32768 * 768];
__device__ float g_buf2[(size_t)32768 * 768];
__device__ float g_o1r[(size_t)32768 * 256];
__device__ float g_o1c[(size_t)32768 * 256];
__device__ float g_o2r[(size_t)32768 * 256];
__device__ float g_o2c[(size_t)32768 * 256];

// ------------------------- 1) fold LN/BN into weights --------------------
__global__ void fold_w_kernel(const float* __restrict__ Wq1, const float* __restrict__ Wkv1,
                              const float* __restrict__ ln1q_w, const float* __restrict__ ln1kv_w,
                              const float* __restrict__ Wq2, const float* __restrict__ Wkv2,
                              const float* __restrict__ ln2q_w, const float* __restrict__ ln2kv_w,
                              const float* __restrict__ Wsc, const float* __restrict__ bn_gamma,
                              const float* __restrict__ bn_var) {
    int idx = blockIdx.x * 256 + threadIdx.x;
    if (idx < 384 * 768) {
        int c = idx / 768, j = idx % 768;
        g_Wbig1[idx] = (j < 256) ? ln1q_w[c] * Wq1[c * 256 + j]
                                 : ln1kv_w[c] * Wkv1[c * 512 + (j - 256)];
    }
    if (idx < 256 * 768) {
        int c = idx / 768, j = idx % 768;
        g_Wbig2[idx] = (j < 256) ? ln2q_w[c] * Wq2[c * 256 + j]
                                 : ln2kv_w[c] * Wkv2[c * 512 + (j - 256)];
    }
    if (idx < 384 * 256) {
        int c = idx / 256, o = idx % 256;
        float g = bn_gamma[o] * rsqrtf(bn_var[o] + EPSF);
        g_Wscf[idx] = Wsc[o * 384 + c] * g;
    }
}

__global__ __launch_bounds__(128)
void fold_cols_kernel(const float* __restrict__ Wq1, const float* __restrict__ Wkv1,
                      const float* __restrict__ ln1q_b, const float* __restrict__ ln1kv_b,
                      const float* __restrict__ Wq2, const float* __restrict__ Wkv2,
                      const float* __restrict__ ln2q_b, const float* __restrict__ ln2kv_b,
                      const float* __restrict__ bout1, const float* __restrict__ bout2,
                      const float* __restrict__ bn_gamma, const float* __restrict__ bn_beta,
                      const float* __restrict__ bn_mean, const float* __restrict__ bn_var) {
    int j = blockIdx.x;
    int t = threadIdx.x;
    float cs1 = 0.f, b1 = 0.f;
    for (int c = t; c < 384; c += 128) {
        cs1 += g_Wbig1[c * 768 + j];
        b1  += (j < 256) ? ln1q_b[c] * Wq1[c * 256 + j]
                         : ln1kv_b[c] * Wkv1[c * 512 + (j - 256)];
    }
    float cs2 = 0.f, b2 = 0.f;
    for (int c = t; c < 256; c += 128) {
        cs2 += g_Wbig2[c * 768 + j];
        b2  += (j < 256) ? ln2q_b[c] * Wq2[c * 256 + j]
                         : ln2kv_b[c] * Wkv2[c * 512 + (j - 256)];
    }
    __shared__ float red[4][128];
    red[0][t] = cs1; red[1][t] = b1; red[2][t] = cs2; red[3][t] = b2;
    __syncthreads();
#pragma unroll
    for (int s = 64; s > 0; s >>= 1) {
        if (t < s) {
#pragma unroll
            for (int v = 0; v < 4; v++) red[v][t] += red[v][t + s];
        }
        __syncthreads();
    }
    if (t == 0) {
        g_colsum1[j] = red[0][0];
        g_bb1[j]     = red[1][0];
        g_colsum2[j] = red[2][0];
        g_bb2[j]     = red[3][0];
        if (j < 256) {
            float g = bn_gamma[j] * rsqrtf(bn_var[j] + EPSF);
            g_btot[j] = (bn_beta[j] - bn_mean[j] * g) + bout1[j] + bout2[j];
        }
    }
}

// ------------------------- f32x2 micro-MMA, 8x16 thread tile -------------
// 64-row tile: As rows are 66 u64 wide. B 16 cols spread as 4x16B at
// 64-col stride. 64 FMA2 per kt per thread.
__device__ __forceinline__ void mma16w(const u64 (*As)[66], const float (*Bs)[256],
                                       u64 (&acc)[8][8], int tx, int ty) {
#pragma unroll 4
    for (int kt = 0; kt < 16; kt++) {
        const ulonglong2* aq = (const ulonglong2*)&As[kt][ty * 8];
        ulonglong2 a01 = aq[0], a23 = aq[1], a45 = aq[2], a67 = aq[3];
        u64 a[8] = {a01.x, a01.y, a23.x, a23.y, a45.x, a45.y, a67.x, a67.y};
        u64 b[8];
#pragma unroll
        for (int q = 0; q < 4; q++) {
            ulonglong2 bv = *(const ulonglong2*)&Bs[kt][q * 64 + tx * 4];
            b[q * 2] = bv.x; b[q * 2 + 1] = bv.y;
        }
#pragma unroll
        for (int i = 0; i < 8; i++)
#pragma unroll
            for (int j = 0; j < 8; j++)
                acc[i][j] = fma2(a[i], b[j], acc[i][j]);
    }
}

// dynamic smem: Asd u64[2][16][66] @0 (16896 B), Bs float[2][16][256] @16896 (32768 B)
#define BS_OFF 16896
#define SMEM_GEMM_BYTES (16896 + 32768)

// ------------------------- 2) projection GEMM ----------------------------
// 64x256 tile per 128-thread CTA, 2 CTAs/SM.
template<int WHICH>
__global__ __launch_bounds__(128, 2)
void proj_gemm_kernel(const float* __restrict__ x) {
    constexpr int K = (WHICH == 0) ? 384 : 256;
    const float* __restrict__ Wf     = (WHICH == 0) ? g_Wbig1   : g_Wbig2;
    const float* __restrict__ colsum = (WHICH == 0) ? g_colsum1 : g_colsum2;
    const float* __restrict__ bb     = (WHICH == 0) ? g_bb1     : g_bb2;
    float* __restrict__ out          = (WHICH == 0) ? g_buf1    : g_buf2;

    extern __shared__ char smem[];
    u64 (*Asd)[16][66] = (u64(*)[16][66])smem;
    float (*Bs)[16][256] = (float(*)[16][256])(smem + BS_OFF);
    const uint32_t sbase = smem_u32(smem);

    const int tid = threadIdx.x;
    const int tx = tid & 15, ty = tid >> 4;   // ty 0..7
    const int s0 = blockIdx.y * 64;
    const int j0 = blockIdx.x * 256;
    const int b = s0 >> 12, p0 = s0 & 4095;
    const float* xb = x + ((size_t)b * K) * 4096 + p0;

    // A staging: kA0/kA1 channel rows, fA = 16B granule within 64-float row
    const int kA0 = tid >> 4, fA = tid & 15;   // kA0 0..7
    const int kA1 = kA0 + 8;

    u64 acc[8][8];
#pragma unroll
    for (int i = 0; i < 8; i++)
#pragma unroll
        for (int j = 0; j < 8; j++) acc[i][j] = 0ULL;

    float asum[4] = {0.f, 0.f, 0.f, 0.f};
    float asq[4]  = {0.f, 0.f, 0.f, 0.f};

    float4 pa0, pa1;
    // prologue: chunk 0
    pa0 = *(const float4*)(xb + (size_t)kA0 * 4096 + fA * 4);
    pa1 = *(const float4*)(xb + (size_t)kA1 * 4096 + fA * 4);
#pragma unroll
    for (int i = 0; i < 8; i++) {
        int g = tid + i * 128;
        int kB = g >> 6, cB = g & 63;
        cp_async16(sbase + BS_OFF + kB * 1024 + cB * 16,
                   Wf + (size_t)kB * 768 + j0 + cB * 4);
    }
    CP_COMMIT();
    asum[0] += pa0.x + pa1.x; asq[0] += pa0.x * pa0.x + pa1.x * pa1.x;
    asum[1] += pa0.y + pa1.y; asq[1] += pa0.y * pa0.y + pa1.y * pa1.y;
    asum[2] += pa0.z + pa1.z; asq[2] += pa0.z * pa0.z + pa1.z * pa1.z;
    asum[3] += pa0.w + pa1.w; asq[3] += pa0.w * pa0.w + pa1.w * pa1.w;
    {
        float* d0 = (float*)&Asd[0][kA0][fA * 4];
        *(float4*)d0       = make_float4(pa0.x, pa0.x, pa0.y, pa0.y);
        *(float4*)(d0 + 4) = make_float4(pa0.z, pa0.z, pa0.w, pa0.w);
        float* d1 = (float*)&Asd[0][kA1][fA * 4];
        *(float4*)d1       = make_float4(pa1.x, pa1.x, pa1.y, pa1.y);
        *(float4*)(d1 + 4) = make_float4(pa1.z, pa1.z, pa1.w, pa1.w);
    }

    int buf = 0;
    for (int c0 = 0; c0 < K; c0 += 16, buf ^= 1) {
        CP_WAIT0();
        __syncthreads();
        bool has_next = (c0 + 16 < K);
        if (has_next) {
            const float* xn = xb + (size_t)(c0 + 16) * 4096;
            pa0 = *(const float4*)(xn + (size_t)kA0 * 4096 + fA * 4);
            pa1 = *(const float4*)(xn + (size_t)kA1 * 4096 + fA * 4);
            uint32_t bdst = sbase + BS_OFF + (buf ^ 1) * 16384;
            const float* wn = Wf + (size_t)(c0 + 16) * 768 + j0;
#pragma unroll
            for (int i = 0; i < 8; i++) {
                int g = tid + i * 128;
                int kB = g >> 6, cB = g & 63;
                cp_async16(bdst + kB * 1024 + cB * 16, wn + (size_t)kB * 768 + cB * 4);
            }
            CP_COMMIT();
        }
        mma16w(Asd[buf], Bs[buf], acc, tx, ty);
        if (has_next) {
            asum[0] += pa0.x + pa1.x; asq[0] += pa0.x * pa0.x + pa1.x * pa1.x;
            asum[1] += pa0.y + pa1.y; asq[1] += pa0.y * pa0.y + pa1.y * pa1.y;
            asum[2] += pa0.z + pa1.z; asq[2] += pa0.z * pa0.z + pa1.z * pa1.z;
            asum[3] += pa0.w + pa1.w; asq[3] += pa0.w * pa0.w + pa1.w * pa1.w;
            float* d0 = (float*)&Asd[buf ^ 1][kA0][fA * 4];
            *(float4*)d0       = make_float4(pa0.x, pa0.x, pa0.y, pa0.y);
            *(float4*)(d0 + 4) = make_float4(pa0.z, pa0.z, pa0.w, pa0.w);
            float* d1 = (float*)&Asd[buf ^ 1][kA1][fA * 4];
            *(float4*)d1       = make_float4(pa1.x, pa1.x, pa1.y, pa1.y);
            *(float4*)(d1 + 4) = make_float4(pa1.z, pa1.z, pa1.w, pa1.w);
        }
    }

    // ---- cross-thread LN-stat reduction through (now idle) smem ----
    __syncthreads();
    float* ps  = (float*)smem;          // [8][64]
    float* pq  = ps + 512;              // [8][64]
    float* muS = pq + 512;              // [64]
    float* rsS = muS + 64;              // [64]
#pragma unroll
    for (int i = 0; i < 4; i++) {
        ps[kA0 * 64 + fA * 4 + i] = asum[i];
        pq[kA0 * 64 + fA * 4 + i] = asq[i];
    }
    __syncthreads();
    if (tid < 64) {
        float s = 0.f, q = 0.f;
#pragma unroll
        for (int r = 0; r < 8; r++) {
            s += ps[r * 64 + tid];
            q += pq[r * 64 + tid];
        }
        float m = s * (1.0f / K);
        float v = q * (1.0f / K) - m * m;
        muS[tid] = m;
        rsS[tid] = rsqrtf(v + EPSF);
    }
    __syncthreads();

#pragma unroll
    for (int i = 0; i < 8; i++) {
        int srow = ty * 8 + i;
        int s = s0 + srow;
        float r = rsS[srow], m = muS[srow];
#pragma unroll
        for (int q = 0; q < 4; q++) {
            int jb = j0 + q * 64 + tx * 4;
            float4 cs = *(const float4*)(colsum + jb);
            float4 bv = *(const float4*)(bb + jb);
            float c0f, c1f, c2f, c3f;
            upk(acc[i][q * 2],     c0f, c1f);
            upk(acc[i][q * 2 + 1], c2f, c3f);
            float4 o;
            o.x = r * (c0f - m * cs.x) + bv.x;
            o.y = r * (c1f - m * cs.y) + bv.y;
            o.z = r * (c2f - m * cs.z) + bv.z;
            o.w = r * (c3f - m * cs.w) + bv.w;
            *(float4*)(out + (size_t)s * 768 + jb) = o;
        }
    }
}

// ------------------------- 3) axial attention ----------------------------
__global__ __launch_bounds__(64)
void attn_kernel() {
    __shared__ __align__(16) float Ks[64][32];
    __shared__ __align__(16) float Vs[64][32];
    const int t = threadIdx.x;
    const int line = blockIdx.x;
    const int b = blockIdx.y >> 3, n = blockIdx.y & 7;
    const int br = blockIdx.z >> 1, dir = blockIdx.z & 1;

    const float* Qb  = br ? g_buf2 : g_buf1;
    const float* KVb = br ? g_buf1 : g_buf2;
    float* ob = br ? (dir ? g_o2c : g_o2r) : (dir ? g_o1c : g_o1r);

    int s_t = (dir == 0) ? (b * 4096 + t * 64 + line) : (b * 4096 + line * 64 + t);

    const float* qp = Qb  + (size_t)s_t * 768 + n * 32;
    const float* kp = KVb + (size_t)s_t * 768 + 256 + n * 32;
    const float* vp = kp + 256;
#pragma unroll
    for (int d4 = 0; d4 < 8; d4++) {
        *(float4*)&Ks[t][d4 * 4] = *(const float4*)(kp + d4 * 4);
        *(float4*)&Vs[t][d4 * 4] = *(const float4*)(vp + d4 * 4);
    }
    u64 q2[16];
#pragma unroll
    for (int d = 0; d < 16; d++) q2[d] = *(const u64*)(qp + 2 * d);
    __syncthreads();

    float sc[64];
    float smax = -1e30f;
#pragma unroll
    for (int j = 0; j < 64; j++) {
        const u64* k2 = (const u64*)Ks[j];
        u64 a = 0ULL;
#pragma unroll
        for (int d = 0; d < 16; d++) a = fma2(q2[d], k2[d], a);
        float lo, hi; upk(a, lo, hi);
        float v = (lo + hi) * 0.17677669529663687f;
        sc[j] = v;
        smax = fmaxf(smax, v);
    }
    float ssum = 0.f;
#pragma unroll
    for (int j = 0; j < 64; j++) {
        float e = __expf(sc[j] - smax);
        sc[j] = e;
        ssum += e;
    }
    float inv = 1.f / ssum;
    u64 o2[16];
#pragma unroll
    for (int d = 0; d < 16; d++) o2[d] = 0ULL;
#pragma unroll
    for (int j = 0; j < 64; j++) {
        u64 pd = dupf(sc[j]);
        const u64* v2 = (const u64*)Vs[j];
#pragma unroll
        for (int d = 0; d < 16; d++) o2[d] = fma2(pd, v2[d], o2[d]);
    }
    u64 iv = dupf(inv);
    float* op = ob + (size_t)s_t * 256 + n * 32;
#pragma unroll
    for (int d = 0; d < 16; d++) {
        u64 r = fma2(o2[d], iv, 0ULL);
        *(u64*)(op + 2 * d) = r;
    }
}

// ------------------------- 4) final fused GEMM ---------------------------
// 64x256 tile per 128-thread CTA, 2 CTAs/SM, K = 384 + 256 + 256.
__global__ __launch_bounds__(128, 2)
void final_gemm_kernel(const float* __restrict__ x1, const float* __restrict__ x2,
                       const float* __restrict__ Wout1, const float* __restrict__ Wout2,
                       float* __restrict__ out) {
    extern __shared__ char smem[];
    u64 (*Asd)[16][66] = (u64(*)[16][66])smem;
    float (*Bs)[16][256] = (float(*)[16][256])(smem + BS_OFF);
    const uint32_t sbase = smem_u32(smem);

    const int tid = threadIdx.x;
    const int tx = tid & 15, ty = tid >> 4;
    const int s0 = blockIdx.x * 64;
    const int b = s0 >> 12, p0 = s0 & 4095;

    const int kA0 = tid >> 4, fA = tid & 15;
    const int kA1 = kA0 + 8;

    u64 acc[8][8];
#pragma unroll
    for (int i = 0; i < 8; i++)
#pragma unroll
        for (int j = 0; j < 8; j++) acc[i][j] = 0ULL;

    int buf = 0;

    // ---------- Phase A: shortcut conv (x1 c-major @ g_Wscf), K = 384 ----
    {
        const float* xb = x1 + ((size_t)b * 384) * 4096 + p0;
        float4 pa0, pa1;
        pa0 = *(const float4*)(xb + (size_t)kA0 * 4096 + fA * 4);
        pa1 = *(const float4*)(xb + (size_t)kA1 * 4096 + fA * 4);
#pragma unroll
        for (int i = 0; i < 8; i++) {
            int g = tid + i * 128;
            int kB = g >> 6, cB = g & 63;
            cp_async16(sbase + BS_OFF + buf * 16384 + kB * 1024 + cB * 16,
                       g_Wscf + (size_t)kB * 256 + cB * 4);
        }
        CP_COMMIT();
        {
            float* d0 = (float*)&Asd[buf][kA0][fA * 4];
            *(float4*)d0       = make_float4(pa0.x, pa0.x, pa0.y, pa0.y);
            *(float4*)(d0 + 4) = make_float4(pa0.z, pa0.z, pa0.w, pa0.w);
            float* d1 = (float*)&Asd[buf][kA1][fA * 4];
            *(float4*)d1       = make_float4(pa1.x, pa1.x, pa1.y, pa1.y);
            *(float4*)(d1 + 4) = make_float4(pa1.z, pa1.z, pa1.w, pa1.w);
        }
        for (int c0 = 0; c0 < 384; c0 += 16, buf ^= 1) {
            CP_WAIT0();
            __syncthreads();
            bool has_next = (c0 + 16 < 384);
            if (has_next) {
                const float* xn = xb + (size_t)(c0 + 16) * 4096;
                pa0 = *(const float4*)(xn + (size_t)kA0 * 4096 + fA * 4);
                pa1 = *(const float4*)(xn + (size_t)kA1 * 4096 + fA * 4);
                uint32_t bdst = sbase + BS_OFF + (buf ^ 1) * 16384;
                const float* wn = g_Wscf + (size_t)(c0 + 16) * 256;
#pragma unroll
                for (int i = 0; i < 8; i++) {
                    int g = tid + i * 128;
                    int kB = g >> 6, cB = g & 63;
                    cp_async16(bdst + kB * 1024 + cB * 16, wn + (size_t)kB * 256 + cB * 4);
                }
                CP_COMMIT();
            }
            mma16w(Asd[buf], Bs[buf], acc, tx, ty);
            if (has_next) {
                float* d0 = (float*)&Asd[buf ^ 1][kA0][fA * 4];
                *(float4*)d0       = make_float4(pa0.x, pa0.x, pa0.y, pa0.y);
                *(float4*)(d0 + 4) = make_float4(pa0.z, pa0.z, pa0.w, pa0.w);
                float* d1 = (float*)&Asd[buf ^ 1][kA1][fA * 4];
                *(float4*)d1       = make_float4(pa1.x, pa1.x, pa1.y, pa1.y);
                *(float4*)(d1 + 4) = make_float4(pa1.z, pa1.z, pa1.w, pa1.w);
            }
        }
    }

    // ---------- Phases B/C: (o_r + o_c) @ Wout, K = 256 each -------------
    // A row-major staging: g = tid + i*128: rowA = g>>2 (0..63), qA = g&3
    const int rowA0 = tid >> 2, qA0 = tid & 3;
    const int rowA1 = (tid + 128) >> 2, qA1 = (tid + 128) & 3;
#pragma unroll
    for (int ph = 0; ph < 2; ph++) {
        const float* o_r = ph ? g_o2r : g_o1r;
        const float* o_c = ph ? g_o2c : g_o1c;
        const float* W   = ph ? Wout2 : Wout1;

        float4 sa0, sa1;
        {
            float4 a = *(const float4*)(o_r + (size_t)(s0 + rowA0) * 256 + qA0 * 4);
            float4 c = *(const float4*)(o_c + (size_t)(s0 + rowA0) * 256 + qA0 * 4);
            sa0 = make_float4(a.x + c.x, a.y + c.y, a.z + c.z, a.w + c.w);
            a = *(const float4*)(o_r + (size_t)(s0 + rowA1) * 256 + qA1 * 4);
            c = *(const float4*)(o_c + (size_t)(s0 + rowA1) * 256 + qA1 * 4);
            sa1 = make_float4(a.x + c.x, a.y + c.y, a.z + c.z, a.w + c.w);
        }
        __syncthreads();  // previous phase readers done before overwriting buf
#pragma unroll
        for (int i = 0; i < 8; i++) {
            int g = tid + i * 128;
            int kB = g >> 6, cB = g & 63;
            cp_async16(sbase + BS_OFF + buf * 16384 + kB * 1024 + cB * 16,
                       W + (size_t)kB * 256 + cB * 4);
        }
        CP_COMMIT();
        {
            Asd[buf][qA0 * 4 + 0][rowA0] = dupf(sa0.x);
            Asd[buf][qA0 * 4 + 1][rowA0] = dupf(sa0.y);
            Asd[buf][qA0 * 4 + 2][rowA0] = dupf(sa0.z);
            Asd[buf][qA0 * 4 + 3][rowA0] = dupf(sa0.w);
            Asd[buf][qA1 * 4 + 0][rowA1] = dupf(sa1.x);
            Asd[buf][qA1 * 4 + 1][rowA1] = dupf(sa1.y);
            Asd[buf][qA1 * 4 + 2][rowA1] = dupf(sa1.z);
            Asd[buf][qA1 * 4 + 3][rowA1] = dupf(sa1.w);
        }
        for (int c0 = 0; c0 < 256; c0 += 16, buf ^= 1) {
            CP_WAIT0();
            __syncthreads();
            bool has_next = (c0 + 16 < 256);
            if (has_next) {
                int cn = c0 + 16;
                float4 a = *(const float4*)(o_r + (size_t)(s0 + rowA0) * 256 + cn + qA0 * 4);
                float4 c = *(const float4*)(o_c + (size_t)(s0 + rowA0) * 256 + cn + qA0 * 4);
                sa0 = make_float4(a.x + c.x, a.y + c.y, a.z + c.z, a.w + c.w);
                a = *(const float4*)(o_r + (size_t)(s0 + rowA1) * 256 + cn + qA1 * 4);
                c = *(const float4*)(o_c + (size_t)(s0 + rowA1) * 256 + cn + qA1 * 4);
                sa1 = make_float4(a.x + c.x, a.y + c.y, a.z + c.z, a.w + c.w);
                uint32_t bdst = sbase + BS_OFF + (buf ^ 1) * 16384;
                const float* wn = W + (size_t)cn * 256;
#pragma unroll
                for (int i = 0; i < 8; i++) {
                    int g = tid + i * 128;
                    int kB = g >> 6, cB = g & 63;
                    cp_async16(bdst + kB * 1024 + cB * 16, wn + (size_t)kB * 256 + cB * 4);
                }
                CP_COMMIT();
            }
            mma16w(Asd[buf], Bs[buf], acc, tx, ty);
            if (has_next) {
                Asd[buf ^ 1][qA0 * 4 + 0][rowA0] = dupf(sa0.x);
                Asd[buf ^ 1][qA0 * 4 + 1][rowA0] = dupf(sa0.y);
                Asd[buf ^ 1][qA0 * 4 + 2][rowA0] = dupf(sa0.z);
                Asd[buf ^ 1][qA0 * 4 + 3][rowA0] = dupf(sa0.w);
                Asd[buf ^ 1][qA1 * 4 + 0][rowA1] = dupf(sa1.x);
                Asd[buf ^ 1][qA1 * 4 + 1][rowA1] = dupf(sa1.y);
                Asd[buf ^ 1][qA1 * 4 + 2][rowA1] = dupf(sa1.z);
                Asd[buf ^ 1][qA1 * 4 + 3][rowA1] = dupf(sa1.w);
            }
        }
    }

    // epilogue: bias + x2 residual, store NCHW (cols = q*64 + tx*4 + c)
    float cf[8][16];
#pragma unroll
    for (int i = 0; i < 8; i++)
#pragma unroll
        for (int j = 0; j < 8; j++)
            upk(acc[i][j], cf[i][2 * j], cf[i][2 * j + 1]);

#pragma unroll
    for (int q = 0; q < 4; q++) {
#pragma unroll
        for (int c = 0; c < 4; c++) {
            int o = q * 64 + tx * 4 + c;
            int l = q * 4 + c;
            size_t base = ((size_t)(b * 256 + o)) * 4096 + p0 + ty * 8;
            float bt = g_btot[o];
            float4 xa  = *(const float4*)(x2 + base);
            float4 xb4 = *(const float4*)(x2 + base + 4);
            float4 r0, r1;
            r0.x = cf[0][l] + bt + xa.x;
            r0.y = cf[1][l] + bt + xa.y;
            r0.z = cf[2][l] + bt + xa.z;
            r0.w = cf[3][l] + bt + xa.w;
            r1.x = cf[4][l] + bt + xb4.x;
            r1.y = cf[5][l] + bt + xb4.y;
            r1.z = cf[6][l] + bt + xb4.z;
            r1.w = cf[7][l] + bt + xb4.w;
            *(float4*)(out + base) = r0;
            *(float4*)(out + base + 4) = r1;
        }
    }
}

// ------------------------- launch ---------------------------------------
extern "C" void kernel_launch(void* const* d_in, const int* in_sizes, int n_in,
                              void* d_out, int out_size) {
    (void)in_sizes; (void)n_in; (void)out_size;
    const float* x1      = (const float*)d_in[0];
    const float* x2      = (const float*)d_in[1];
    const float* ln1q_w  = (const float*)d_in[2];
    const float* ln1q_b  = (const float*)d_in[3];
    const float* ln2kv_w = (const float*)d_in[4];
    const float* ln2kv_b = (const float*)d_in[5];
    const float* Wq1     = (const float*)d_in[6];
    const float* Wkv2    = (const float*)d_in[7];
    const float* Wout1   = (const float*)d_in[8];
    const float* bout1   = (const float*)d_in[9];
    const float* ln2q_w  = (const float*)d_in[10];
    const float* ln2q_b  = (const float*)d_in[11];
    const float* ln1kv_w = (const float*)d_in[12];
    const float* ln1kv_b = (const float*)d_in[13];
    const float* Wq2     = (const float*)d_in[14];
    const float* Wkv1    = (const float*)d_in[15];
    const float* Wout2   = (const float*)d_in[16];
    const float* bout2   = (const float*)d_in[17];
    const float* Wsc     = (const float*)d_in[18];
    const float* bn_g    = (const float*)d_in[19];
    const float* bn_b    = (const float*)d_in[20];
    const float* bn_m    = (const float*)d_in[21];
    const float* bn_v    = (const float*)d_in[22];
    float* out = (float*)d_out;

    cudaFuncSetAttribute(proj_gemm_kernel<0>, cudaFuncAttributeMaxDynamicSharedMemorySize, SMEM_GEMM_BYTES);
    cudaFuncSetAttribute(proj_gemm_kernel<1>, cudaFuncAttributeMaxDynamicSharedMemorySize, SMEM_GEMM_BYTES);
    cudaFuncSetAttribute(final_gemm_kernel,   cudaFuncAttributeMaxDynamicSharedMemorySize, SMEM_GEMM_BYTES);

    fold_w_kernel<<<1152, 256>>>(Wq1, Wkv1, ln1q_w, ln1kv_w,
                                 Wq2, Wkv2, ln2q_w, ln2kv_w,
                                 Wsc, bn_g, bn_v);
    fold_cols_kernel<<<768, 128>>>(Wq1, Wkv1, ln1q_b, ln1kv_b,
                                   Wq2, Wkv2, ln2q_b, ln2kv_b,
                                   bout1, bout2, bn_g, bn_b, bn_m, bn_v);
    proj_gemm_kernel<0><<<dim3(3, 512), 128, SMEM_GEMM_BYTES>>>(x1);
    proj_gemm_kernel<1><<<dim3(3, 512), 128, SMEM_GEMM_BYTES>>>(x2);
    attn_kernel<<<dim3(64, 64, 4), 64>>>();
    final_gemm_kernel<<<512, 128, SMEM_GEMM_BYTES>>>(x1, x2, Wout1, Wout2, out);
}

// round 15
// speedup vs baseline: 1.6232x; 1.0211x over previous
#include <cuda_runtime.h>
#include <cstdint>
#include <cstddef>

#define EPSF 1e-5f

typedef unsigned long long u64;

// ------------------------- packed f32x2 helpers -------------------------
__device__ __forceinline__ u64 pk(float lo, float hi) {
    u64 r; asm("mov.b64 %0, {%1, %2};" : "=l"(r) : "f"(lo), "f"(hi)); return r;
}
__device__ __forceinline__ u64 dupf(float v) { return pk(v, v); }
__device__ __forceinline__ u64 fma2(u64 a, u64 b, u64 c) {
    u64 d; asm("fma.rn.f32x2 %0, %1, %2, %3;" : "=l"(d) : "l"(a), "l"(b), "l"(c)); return d;
}
__device__ __forceinline__ void upk(u64 v, float& lo, float& hi) {
    asm("mov.b64 {%0, %1}, %2;" : "=f"(lo), "=f"(hi) : "l"(v));
}

// ------------------------- cp.async helpers ------------------------------
__device__ __forceinline__ uint32_t smem_u32(const void* p) {
    uint32_t a;
    asm("{ .reg .u64 t; cvta.to.shared.u64 t, %1; cvt.u32.u64 %0, t; }" : "=r"(a) : "l"(p));
    return a;
}
__device__ __forceinline__ void cp_async16(uint32_t dst, const void* src) {
    asm volatile("cp.async.cg.shared.global [%0], [%1], 16;" :: "r"(dst), "l"(src) : "memory");
}
#define CP_COMMIT() asm volatile("cp.async.commit_group;" ::: "memory")
#define CP_WAIT0()  asm volatile("cp.async.wait_group 0;" ::: "memory")

// ------------------------- scratch (static device) ----------------------
__device__ float g_Wbig1[384 * 768];
__device__ float g_Wbig2[256 * 768];
__device__ float g_Wscf[384 * 256];
__device__ float g_colsum1[768], g_bb1[768];
__device__ float g_colsum2[768], g_bb2[768];
__device__ float g_btot[256];
__device__ float g_buf1[(size_t)32768 * 768];
__device__ float g_buf2[(size_t)32768 * 768];
__device__ float g_o1r[(size_t)32768 * 256];
__device__ float g_o1c[(size_t)32768 * 256];
__device__ float g_o2r[(size_t)32768 * 256];
__device__ float g_o2c[(size_t)32768 * 256];

// ------------------------- 1) fold LN/BN into weights --------------------
__global__ void fold_w_kernel(const float* __restrict__ Wq1, const float* __restrict__ Wkv1,
                              const float* __restrict__ ln1q_w, const float* __restrict__ ln1kv_w,
                              const float* __restrict__ Wq2, const float* __restrict__ Wkv2,
                              const float* __restrict__ ln2q_w, const float* __restrict__ ln2kv_w,
                              const float* __restrict__ Wsc, const float* __restrict__ bn_gamma,
                              const float* __restrict__ bn_var) {
    int idx = blockIdx.x * 256 + threadIdx.x;
    if (idx < 384 * 768) {
        int c = idx / 768, j = idx % 768;
        g_Wbig1[idx] = (j < 256) ? ln1q_w[c] * Wq1[c * 256 + j]
                                 : ln1kv_w[c] * Wkv1[c * 512 + (j - 256)];
    }
    if (idx < 256 * 768) {
        int c = idx / 768, j = idx % 768;
        g_Wbig2[idx] = (j < 256) ? ln2q_w[c] * Wq2[c * 256 + j]
                                 : ln2kv_w[c] * Wkv2[c * 512 + (j - 256)];
    }
    if (idx < 384 * 256) {
        int c = idx / 256, o = idx % 256;
        float g = bn_gamma[o] * rsqrtf(bn_var[o] + EPSF);
        g_Wscf[idx] = Wsc[o * 384 + c] * g;
    }
}

__global__ __launch_bounds__(128)
void fold_cols_kernel(const float* __restrict__ Wq1, const float* __restrict__ Wkv1,
                      const float* __restrict__ ln1q_b, const float* __restrict__ ln1kv_b,
                      const float* __restrict__ Wq2, const float* __restrict__ Wkv2,
                      const float* __restrict__ ln2q_b, const float* __restrict__ ln2kv_b,
                      const float* __restrict__ bout1, const float* __restrict__ bout2,
                      const float* __restrict__ bn_gamma, const float* __restrict__ bn_beta,
                      const float* __restrict__ bn_mean, const float* __restrict__ bn_var) {
    int j = blockIdx.x;
    int t = threadIdx.x;
    float cs1 = 0.f, b1 = 0.f;
    for (int c = t; c < 384; c += 128) {
        cs1 += g_Wbig1[c * 768 + j];
        b1  += (j < 256) ? ln1q_b[c] * Wq1[c * 256 + j]
                         : ln1kv_b[c] * Wkv1[c * 512 + (j - 256)];
    }
    float cs2 = 0.f, b2 = 0.f;
    for (int c = t; c < 256; c += 128) {
        cs2 += g_Wbig2[c * 768 + j];
        b2  += (j < 256) ? ln2q_b[c] * Wq2[c * 256 + j]
                         : ln2kv_b[c] * Wkv2[c * 512 + (j - 256)];
    }
    __shared__ float red[4][128];
    red[0][t] = cs1; red[1][t] = b1; red[2][t] = cs2; red[3][t] = b2;
    __syncthreads();
#pragma unroll
    for (int s = 64; s > 0; s >>= 1) {
        if (t < s) {
#pragma unroll
            for (int v = 0; v < 4; v++) red[v][t] += red[v][t + s];
        }
        __syncthreads();
    }
    if (t == 0) {
        g_colsum1[j] = red[0][0];
        g_bb1[j]     = red[1][0];
        g_colsum2[j] = red[2][0];
        g_bb2[j]     = red[3][0];
        if (j < 256) {
            float g = bn_gamma[j] * rsqrtf(bn_var[j] + EPSF);
            g_btot[j] = (bn_beta[j] - bn_mean[j] * g) + bout1[j] + bout2[j];
        }
    }
}

// ------------------------- f32x2 micro-MMA, 8x16 thread tile -------------
__device__ __forceinline__ void mma16w(const u64 (*As)[66], const float (*Bs)[256],
                                       u64 (&acc)[8][8], int tx, int ty) {
#pragma unroll 4
    for (int kt = 0; kt < 16; kt++) {
        const ulonglong2* aq = (const ulonglong2*)&As[kt][ty * 8];
        ulonglong2 a01 = aq[0], a23 = aq[1], a45 = aq[2], a67 = aq[3];
        u64 a[8] = {a01.x, a01.y, a23.x, a23.y, a45.x, a45.y, a67.x, a67.y};
        u64 b[8];
#pragma unroll
        for (int q = 0; q < 4; q++) {
            ulonglong2 bv = *(const ulonglong2*)&Bs[kt][q * 64 + tx * 4];
            b[q * 2] = bv.x; b[q * 2 + 1] = bv.y;
        }
#pragma unroll
        for (int i = 0; i < 8; i++)
#pragma unroll
            for (int j = 0; j < 8; j++)
                acc[i][j] = fma2(a[i], b[j], acc[i][j]);
    }
}

// dynamic smem: Asd u64[2][16][66] @0 (16896 B), Bs float[2][16][256] @16896 (32768 B)
#define BS_OFF 16896
#define SMEM_GEMM_BYTES (16896 + 32768)

// ------------------------- 2) projection GEMM body -----------------------
// 64x256 tile per 128-thread CTA.
template<int WHICH>
__device__ __forceinline__ void proj_body(const float* __restrict__ x) {
    constexpr int K = (WHICH == 0) ? 384 : 256;
    const float* __restrict__ Wf     = (WHICH == 0) ? g_Wbig1   : g_Wbig2;
    const float* __restrict__ colsum = (WHICH == 0) ? g_colsum1 : g_colsum2;
    const float* __restrict__ bb     = (WHICH == 0) ? g_bb1     : g_bb2;
    float* __restrict__ out          = (WHICH == 0) ? g_buf1    : g_buf2;

    extern __shared__ char smem[];
    u64 (*Asd)[16][66] = (u64(*)[16][66])smem;
    float (*Bs)[16][256] = (float(*)[16][256])(smem + BS_OFF);
    const uint32_t sbase = smem_u32(smem);

    const int tid = threadIdx.x;
    const int tx = tid & 15, ty = tid >> 4;
    const int s0 = blockIdx.y * 64;
    const int j0 = blockIdx.x * 256;
    const int b = s0 >> 12, p0 = s0 & 4095;
    const float* xb = x + ((size_t)b * K) * 4096 + p0;

    const int kA0 = tid >> 4, fA = tid & 15;
    const int kA1 = kA0 + 8;

    u64 acc[8][8];
#pragma unroll
    for (int i = 0; i < 8; i++)
#pragma unroll
        for (int j = 0; j < 8; j++) acc[i][j] = 0ULL;

    float asum[4] = {0.f, 0.f, 0.f, 0.f};
    float asq[4]  = {0.f, 0.f, 0.f, 0.f};

    float4 pa0, pa1;
    pa0 = *(const float4*)(xb + (size_t)kA0 * 4096 + fA * 4);
    pa1 = *(const float4*)(xb + (size_t)kA1 * 4096 + fA * 4);
#pragma unroll
    for (int i = 0; i < 8; i++) {
        int g = tid + i * 128;
        int kB = g >> 6, cB = g & 63;
        cp_async16(sbase + BS_OFF + kB * 1024 + cB * 16,
                   Wf + (size_t)kB * 768 + j0 + cB * 4);
    }
    CP_COMMIT();
    asum[0] += pa0.x + pa1.x; asq[0] += pa0.x * pa0.x + pa1.x * pa1.x;
    asum[1] += pa0.y + pa1.y; asq[1] += pa0.y * pa0.y + pa1.y * pa1.y;
    asum[2] += pa0.z + pa1.z; asq[2] += pa0.z * pa0.z + pa1.z * pa1.z;
    asum[3] += pa0.w + pa1.w; asq[3] += pa0.w * pa0.w + pa1.w * pa1.w;
    {
        float* d0 = (float*)&Asd[0][kA0][fA * 4];
        *(float4*)d0       = make_float4(pa0.x, pa0.x, pa0.y, pa0.y);
        *(float4*)(d0 + 4) = make_float4(pa0.z, pa0.z, pa0.w, pa0.w);
        float* d1 = (float*)&Asd[0][kA1][fA * 4];
        *(float4*)d1       = make_float4(pa1.x, pa1.x, pa1.y, pa1.y);
        *(float4*)(d1 + 4) = make_float4(pa1.z, pa1.z, pa1.w, pa1.w);
    }

    int buf = 0;
    for (int c0 = 0; c0 < K; c0 += 16, buf ^= 1) {
        CP_WAIT0();
        __syncthreads();
        bool has_next = (c0 + 16 < K);
        if (has_next) {
            const float* xn = xb + (size_t)(c0 + 16) * 4096;
            pa0 = *(const float4*)(xn + (size_t)kA0 * 4096 + fA * 4);
            pa1 = *(const float4*)(xn + (size_t)kA1 * 4096 + fA * 4);
            uint32_t bdst = sbase + BS_OFF + (buf ^ 1) * 16384;
            const float* wn = Wf + (size_t)(c0 + 16) * 768 + j0;
#pragma unroll
            for (int i = 0; i < 8; i++) {
                int g = tid + i * 128;
                int kB = g >> 6, cB = g & 63;
                cp_async16(bdst + kB * 1024 + cB * 16, wn + (size_t)kB * 768 + cB * 4);
            }
            CP_COMMIT();
        }
        mma16w(Asd[buf], Bs[buf], acc, tx, ty);
        if (has_next) {
            asum[0] += pa0.x + pa1.x; asq[0] += pa0.x * pa0.x + pa1.x * pa1.x;
            asum[1] += pa0.y + pa1.y; asq[1] += pa0.y * pa0.y + pa1.y * pa1.y;
            asum[2] += pa0.z + pa1.z; asq[2] += pa0.z * pa0.z + pa1.z * pa1.z;
            asum[3] += pa0.w + pa1.w; asq[3] += pa0.w * pa0.w + pa1.w * pa1.w;
            float* d0 = (float*)&Asd[buf ^ 1][kA0][fA * 4];
            *(float4*)d0       = make_float4(pa0.x, pa0.x, pa0.y, pa0.y);
            *(float4*)(d0 + 4) = make_float4(pa0.z, pa0.z, pa0.w, pa0.w);
            float* d1 = (float*)&Asd[buf ^ 1][kA1][fA * 4];
            *(float4*)d1       = make_float4(pa1.x, pa1.x, pa1.y, pa1.y);
            *(float4*)(d1 + 4) = make_float4(pa1.z, pa1.z, pa1.w, pa1.w);
        }
    }

    // ---- cross-thread LN-stat reduction through (now idle) smem ----
    __syncthreads();
    float* ps  = (float*)smem;          // [8][64]
    float* pq  = ps + 512;              // [8][64]
    float* muS = pq + 512;              // [64]
    float* rsS = muS + 64;              // [64]
#pragma unroll
    for (int i = 0; i < 4; i++) {
        ps[kA0 * 64 + fA * 4 + i] = asum[i];
        pq[kA0 * 64 + fA * 4 + i] = asq[i];
    }
    __syncthreads();
    if (tid < 64) {
        float s = 0.f, q = 0.f;
#pragma unroll
        for (int r = 0; r < 8; r++) {
            s += ps[r * 64 + tid];
            q += pq[r * 64 + tid];
        }
        float m = s * (1.0f / K);
        float v = q * (1.0f / K) - m * m;
        muS[tid] = m;
        rsS[tid] = rsqrtf(v + EPSF);
    }
    __syncthreads();

#pragma unroll
    for (int i = 0; i < 8; i++) {
        int srow = ty * 8 + i;
        int s = s0 + srow;
        float r = rsS[srow], m = muS[srow];
#pragma unroll
        for (int q = 0; q < 4; q++) {
            int jb = j0 + q * 64 + tx * 4;
            float4 cs = *(const float4*)(colsum + jb);
            float4 bv = *(const float4*)(bb + jb);
            float c0f, c1f, c2f, c3f;
            upk(acc[i][q * 2],     c0f, c1f);
            upk(acc[i][q * 2 + 1], c2f, c3f);
            float4 o;
            o.x = r * (c0f - m * cs.x) + bv.x;
            o.y = r * (c1f - m * cs.y) + bv.y;
            o.z = r * (c2f - m * cs.z) + bv.z;
            o.w = r * (c3f - m * cs.w) + bv.w;
            *(float4*)(out + (size_t)s * 768 + jb) = o;
        }
    }
}

// unified projection launch: z = 0 -> branch 1 (K=384, x1), z = 1 -> branch 2
__global__ __launch_bounds__(128, 2)
void proj_both_kernel(const float* __restrict__ x1, const float* __restrict__ x2) {
    if (blockIdx.z == 0) proj_body<0>(x1);
    else                 proj_body<1>(x2);
}

// ------------------------- 3) axial attention ----------------------------
__global__ __launch_bounds__(64)
void attn_kernel() {
    __shared__ __align__(16) float Ks[64][32];
    __shared__ __align__(16) float Vs[64][32];
    const int t = threadIdx.x;
    const int line = blockIdx.x;
    const int b = blockIdx.y >> 3, n = blockIdx.y & 7;
    const int br = blockIdx.z >> 1, dir = blockIdx.z & 1;

    const float* Qb  = br ? g_buf2 : g_buf1;
    const float* KVb = br ? g_buf1 : g_buf2;
    float* ob = br ? (dir ? g_o2c : g_o2r) : (dir ? g_o1c : g_o1r);

    int s_t = (dir == 0) ? (b * 4096 + t * 64 + line) : (b * 4096 + line * 64 + t);

    const float* qp = Qb  + (size_t)s_t * 768 + n * 32;
    const float* kp = KVb + (size_t)s_t * 768 + 256 + n * 32;
    const float* vp = kp + 256;
#pragma unroll
    for (int d4 = 0; d4 < 8; d4++) {
        *(float4*)&Ks[t][d4 * 4] = *(const float4*)(kp + d4 * 4);
        *(float4*)&Vs[t][d4 * 4] = *(const float4*)(vp + d4 * 4);
    }
    u64 q2[16];
#pragma unroll
    for (int d = 0; d < 16; d++) q2[d] = *(const u64*)(qp + 2 * d);
    __syncthreads();

    float sc[64];
    float smax = -1e30f;
#pragma unroll
    for (int j = 0; j < 64; j++) {
        const u64* k2 = (const u64*)Ks[j];
        u64 a = 0ULL;
#pragma unroll
        for (int d = 0; d < 16; d++) a = fma2(q2[d], k2[d], a);
        float lo, hi; upk(a, lo, hi);
        float v = (lo + hi) * 0.17677669529663687f;
        sc[j] = v;
        smax = fmaxf(smax, v);
    }
    float ssum = 0.f;
#pragma unroll
    for (int j = 0; j < 64; j++) {
        float e = __expf(sc[j] - smax);
        sc[j] = e;
        ssum += e;
    }
    float inv = 1.f / ssum;
    u64 o2[16];
#pragma unroll
    for (int d = 0; d < 16; d++) o2[d] = 0ULL;
#pragma unroll
    for (int j = 0; j < 64; j++) {
        u64 pd = dupf(sc[j]);
        const u64* v2 = (const u64*)Vs[j];
#pragma unroll
        for (int d = 0; d < 16; d++) o2[d] = fma2(pd, v2[d], o2[d]);
    }
    u64 iv = dupf(inv);
    float* op = ob + (size_t)s_t * 256 + n * 32;
#pragma unroll
    for (int d = 0; d < 16; d++) {
        u64 r = fma2(o2[d], iv, 0ULL);
        *(u64*)(op + 2 * d) = r;
    }
}

// ------------------------- 4) final fused GEMM ---------------------------
__global__ __launch_bounds__(128, 2)
void final_gemm_kernel(const float* __restrict__ x1, const float* __restrict__ x2,
                       const float* __restrict__ Wout1, const float* __restrict__ Wout2,
                       float* __restrict__ out) {
    extern __shared__ char smem[];
    u64 (*Asd)[16][66] = (u64(*)[16][66])smem;
    float (*Bs)[16][256] = (float(*)[16][256])(smem + BS_OFF);
    const uint32_t sbase = smem_u32(smem);

    const int tid = threadIdx.x;
    const int tx = tid & 15, ty = tid >> 4;
    const int s0 = blockIdx.x * 64;
    const int b = s0 >> 12, p0 = s0 & 4095;

    const int kA0 = tid >> 4, fA = tid & 15;
    const int kA1 = kA0 + 8;

    u64 acc[8][8];
#pragma unroll
    for (int i = 0; i < 8; i++)
#pragma unroll
        for (int j = 0; j < 8; j++) acc[i][j] = 0ULL;

    int buf = 0;

    // ---------- Phase A: shortcut conv (x1 c-major @ g_Wscf), K = 384 ----
    {
        const float* xb = x1 + ((size_t)b * 384) * 4096 + p0;
        float4 pa0, pa1;
        pa0 = *(const float4*)(xb + (size_t)kA0 * 4096 + fA * 4);
        pa1 = *(const float4*)(xb + (size_t)kA1 * 4096 + fA * 4);
#pragma unroll
        for (int i = 0; i < 8; i++) {
            int g = tid + i * 128;
            int kB = g >> 6, cB = g & 63;
            cp_async16(sbase + BS_OFF + buf * 16384 + kB * 1024 + cB * 16,
                       g_Wscf + (size_t)kB * 256 + cB * 4);
        }
        CP_COMMIT();
        {
            float* d0 = (float*)&Asd[buf][kA0][fA * 4];
            *(float4*)d0       = make_float4(pa0.x, pa0.x, pa0.y, pa0.y);
            *(float4*)(d0 + 4) = make_float4(pa0.z, pa0.z, pa0.w, pa0.w);
            float* d1 = (float*)&Asd[buf][kA1][fA * 4];
            *(float4*)d1       = make_float4(pa1.x, pa1.x, pa1.y, pa1.y);
            *(float4*)(d1 + 4) = make_float4(pa1.z, pa1.z, pa1.w, pa1.w);
        }
        for (int c0 = 0; c0 < 384; c0 += 16, buf ^= 1) {
            CP_WAIT0();
            __syncthreads();
            bool has_next = (c0 + 16 < 384);
            if (has_next) {
                const float* xn = xb + (size_t)(c0 + 16) * 4096;
                pa0 = *(const float4*)(xn + (size_t)kA0 * 4096 + fA * 4);
                pa1 = *(const float4*)(xn + (size_t)kA1 * 4096 + fA * 4);
                uint32_t bdst = sbase + BS_OFF + (buf ^ 1) * 16384;
                const float* wn = g_Wscf + (size_t)(c0 + 16) * 256;
#pragma unroll
                for (int i = 0; i < 8; i++) {
                    int g = tid + i * 128;
                    int kB = g >> 6, cB = g & 63;
                    cp_async16(bdst + kB * 1024 + cB * 16, wn + (size_t)kB * 256 + cB * 4);
                }
                CP_COMMIT();
            }
            mma16w(Asd[buf], Bs[buf], acc, tx, ty);
            if (has_next) {
                float* d0 = (float*)&Asd[buf ^ 1][kA0][fA * 4];
                *(float4*)d0       = make_float4(pa0.x, pa0.x, pa0.y, pa0.y);
                *(float4*)(d0 + 4) = make_float4(pa0.z, pa0.z, pa0.w, pa0.w);
                float* d1 = (float*)&Asd[buf ^ 1][kA1][fA * 4];
                *(float4*)d1       = make_float4(pa1.x, pa1.x, pa1.y, pa1.y);
                *(float4*)(d1 + 4) = make_float4(pa1.z, pa1.z, pa1.w, pa1.w);
            }
        }
    }

    // ---------- Phases B/C: (o_r + o_c) @ Wout, K = 256 each -------------
    const int rowA0 = tid >> 2, qA0 = tid & 3;
    const int rowA1 = (tid + 128) >> 2, qA1 = (tid + 128) & 3;
#pragma unroll
    for (int ph = 0; ph < 2; ph++) {
        const float* o_r = ph ? g_o2r : g_o1r;
        const float* o_c = ph ? g_o2c : g_o1c;
        const float* W   = ph ? Wout2 : Wout1;

        float4 sa0, sa1;
        {
            float4 a = *(const float4*)(o_r + (size_t)(s0 + rowA0) * 256 + qA0 * 4);
            float4 c = *(const float4*)(o_c + (size_t)(s0 + rowA0) * 256 + qA0 * 4);
            sa0 = make_float4(a.x + c.x, a.y + c.y, a.z + c.z, a.w + c.w);
            a = *(const float4*)(o_r + (size_t)(s0 + rowA1) * 256 + qA1 * 4);
            c = *(const float4*)(o_c + (size_t)(s0 + rowA1) * 256 + qA1 * 4);
            sa1 = make_float4(a.x + c.x, a.y + c.y, a.z + c.z, a.w + c.w);
        }
        __syncthreads();  // previous phase readers done before overwriting buf
#pragma unroll
        for (int i = 0; i < 8; i++) {
            int g = tid + i * 128;
            int kB = g >> 6, cB = g & 63;
            cp_async16(sbase + BS_OFF + buf * 16384 + kB * 1024 + cB * 16,
                       W + (size_t)kB * 256 + cB * 4);
        }
        CP_COMMIT();
        {
            Asd[buf][qA0 * 4 + 0][rowA0] = dupf(sa0.x);
            Asd[buf][qA0 * 4 + 1][rowA0] = dupf(sa0.y);
            Asd[buf][qA0 * 4 + 2][rowA0] = dupf(sa0.z);
            Asd[buf][qA0 * 4 + 3][rowA0] = dupf(sa0.w);
            Asd[buf][qA1 * 4 + 0][rowA1] = dupf(sa1.x);
            Asd[buf][qA1 * 4 + 1][rowA1] = dupf(sa1.y);
            Asd[buf][qA1 * 4 + 2][rowA1] = dupf(sa1.z);
            Asd[buf][qA1 * 4 + 3][rowA1] = dupf(sa1.w);
        }
        for (int c0 = 0; c0 < 256; c0 += 16, buf ^= 1) {
            CP_WAIT0();
            __syncthreads();
            bool has_next = (c0 + 16 < 256);
            if (has_next) {
                int cn = c0 + 16;
                float4 a = *(const float4*)(o_r + (size_t)(s0 + rowA0) * 256 + cn + qA0 * 4);
                float4 c = *(const float4*)(o_c + (size_t)(s0 + rowA0) * 256 + cn + qA0 * 4);
                sa0 = make_float4(a.x + c.x, a.y + c.y, a.z + c.z, a.w + c.w);
                a = *(const float4*)(o_r + (size_t)(s0 + rowA1) * 256 + cn + qA1 * 4);
                c = *(const float4*)(o_c + (size_t)(s0 + rowA1) * 256 + cn + qA1 * 4);
                sa1 = make_float4(a.x + c.x, a.y + c.y, a.z + c.z, a.w + c.w);
                uint32_t bdst = sbase + BS_OFF + (buf ^ 1) * 16384;
                const float* wn = W + (size_t)cn * 256;
#pragma unroll
                for (int i = 0; i < 8; i++) {
                    int g = tid + i * 128;
                    int kB = g >> 6, cB = g & 63;
                    cp_async16(bdst + kB * 1024 + cB * 16, wn + (size_t)kB * 256 + cB * 4);
                }
                CP_COMMIT();
            }
            mma16w(Asd[buf], Bs[buf], acc, tx, ty);
            if (has_next) {
                Asd[buf ^ 1][qA0 * 4 + 0][rowA0] = dupf(sa0.x);
                Asd[buf ^ 1][qA0 * 4 + 1][rowA0] = dupf(sa0.y);
                Asd[buf ^ 1][qA0 * 4 + 2][rowA0] = dupf(sa0.z);
                Asd[buf ^ 1][qA0 * 4 + 3][rowA0] = dupf(sa0.w);
                Asd[buf ^ 1][qA1 * 4 + 0][rowA1] = dupf(sa1.x);
                Asd[buf ^ 1][qA1 * 4 + 1][rowA1] = dupf(sa1.y);
                Asd[buf ^ 1][qA1 * 4 + 2][rowA1] = dupf(sa1.z);
                Asd[buf ^ 1][qA1 * 4 + 3][rowA1] = dupf(sa1.w);
            }
        }
    }

    // epilogue: bias + x2 residual, store NCHW (cols = q*64 + tx*4 + c)
    float cf[8][16];
#pragma unroll
    for (int i = 0; i < 8; i++)
#pragma unroll
        for (int j = 0; j < 8; j++)
            upk(acc[i][j], cf[i][2 * j], cf[i][2 * j + 1]);

#pragma unroll
    for (int q = 0; q < 4; q++) {
#pragma unroll
        for (int c = 0; c < 4; c++) {
            int o = q * 64 + tx * 4 + c;
            int l = q * 4 + c;
            size_t base = ((size_t)(b * 256 + o)) * 4096 + p0 + ty * 8;
            float bt = g_btot[o];
            float4 xa  = *(const float4*)(x2 + base);
            float4 xb4 = *(const float4*)(x2 + base + 4);
            float4 r0, r1;
            r0.x = cf[0][l] + bt + xa.x;
            r0.y = cf[1][l] + bt + xa.y;
            r0.z = cf[2][l] + bt + xa.z;
            r0.w = cf[3][l] + bt + xa.w;
            r1.x = cf[4][l] + bt + xb4.x;
            r1.y = cf[5][l] + bt + xb4.y;
            r1.z = cf[6][l] + bt + xb4.z;
            r1.w = cf[7][l] + bt + xb4.w;
            *(float4*)(out + base) = r0;
            *(float4*)(out + base + 4) = r1;
        }
    }
}

// ------------------------- launch ---------------------------------------
extern "C" void kernel_launch(void* const* d_in, const int* in_sizes, int n_in,
                              void* d_out, int out_size) {
    (void)in_sizes; (void)n_in; (void)out_size;
    const float* x1      = (const float*)d_in[0];
    const float* x2      = (const float*)d_in[1];
    const float* ln1q_w  = (const float*)d_in[2];
    const float* ln1q_b  = (const float*)d_in[3];
    const float* ln2kv_w = (const float*)d_in[4];
    const float* ln2kv_b = (const float*)d_in[5];
    const float* Wq1     = (const float*)d_in[6];
    const float* Wkv2    = (const float*)d_in[7];
    const float* Wout1   = (const float*)d_in[8];
    const float* bout1   = (const float*)d_in[9];
    const float* ln2q_w  = (const float*)d_in[10];
    const float* ln2q_b  = (const float*)d_in[11];
    const float* ln1kv_w = (const float*)d_in[12];
    const float* ln1kv_b = (const float*)d_in[13];
    const float* Wq2     = (const float*)d_in[14];
    const float* Wkv1    = (const float*)d_in[15];
    const float* Wout2   = (const float*)d_in[16];
    const float* bout2   = (const float*)d_in[17];
    const float* Wsc     = (const float*)d_in[18];
    const float* bn_g    = (const float*)d_in[19];
    const float* bn_b    = (const float*)d_in[20];
    const float* bn_m    = (const float*)d_in[21];
    const float* bn_v    = (const float*)d_in[22];
    float* out = (float*)d_out;

    cudaFuncSetAttribute(proj_both_kernel, cudaFuncAttributeMaxDynamicSharedMemorySize, SMEM_GEMM_BYTES);
    cudaFuncSetAttribute(final_gemm_kernel, cudaFuncAttributeMaxDynamicSharedMemorySize, SMEM_GEMM_BYTES);

    fold_w_kernel<<<1152, 256>>>(Wq1, Wkv1, ln1q_w, ln1kv_w,
                                 Wq2, Wkv2, ln2q_w, ln2kv_w,
                                 Wsc, bn_g, bn_v);
    fold_cols_kernel<<<768, 128>>>(Wq1, Wkv1, ln1q_b, ln1kv_b,
                                   Wq2, Wkv2, ln2q_b, ln2kv_b,
                                   bout1, bout2, bn_g, bn_b, bn_m, bn_v);
    proj_both_kernel<<<dim3(3, 512, 2), 128, SMEM_GEMM_BYTES>>>(x1, x2);
    attn_kernel<<<dim3(64, 64, 4), 64>>>();
    final_gemm_kernel<<<512, 128, SMEM_GEMM_BYTES>>>(x1, x2, Wout1, Wout2, out);
}

// round 16
// speedup vs baseline: 1.6943x; 1.0438x over previous
#include <cuda_runtime.h>
#include <cstdint>
#include <cstddef>

#define EPSF 1e-5f

typedef unsigned long long u64;

// ------------------------- packed f32x2 helpers -------------------------
__device__ __forceinline__ u64 pk(float lo, float hi) {
    u64 r; asm("mov.b64 %0, {%1, %2};" : "=l"(r) : "f"(lo), "f"(hi)); return r;
}
__device__ __forceinline__ u64 dupf(float v) { return pk(v, v); }
__device__ __forceinline__ u64 fma2(u64 a, u64 b, u64 c) {
    u64 d; asm("fma.rn.f32x2 %0, %1, %2, %3;" : "=l"(d) : "l"(a), "l"(b), "l"(c)); return d;
}
__device__ __forceinline__ void upk(u64 v, float& lo, float& hi) {
    asm("mov.b64 {%0, %1}, %2;" : "=f"(lo), "=f"(hi) : "l"(v));
}

// ------------------------- cp.async helpers ------------------------------
__device__ __forceinline__ uint32_t smem_u32(const void* p) {
    uint32_t a;
    asm("{ .reg .u64 t; cvta.to.shared.u64 t, %1; cvt.u32.u64 %0, t; }" : "=r"(a) : "l"(p));
    return a;
}
__device__ __forceinline__ void cp_async16(uint32_t dst, const void* src) {
    asm volatile("cp.async.cg.shared.global [%0], [%1], 16;" :: "r"(dst), "l"(src) : "memory");
}
#define CP_COMMIT() asm volatile("cp.async.commit_group;" ::: "memory")
#define CP_WAIT0()  asm volatile("cp.async.wait_group 0;" ::: "memory")

// ------------------------- scratch (static device) ----------------------
__device__ float g_Wbig1[384 * 768];
__device__ float g_Wbig2[256 * 768];
__device__ float g_Wscf[384 * 256];
__device__ float g_colsum1[768], g_bb1[768];
__device__ float g_colsum2[768], g_bb2[768];
__device__ float g_btot[256];
__device__ float g_buf1[(size_t)32768 * 768];
__device__ float g_buf2[(size_t)32768 * 768];
__device__ float g_o1r[(size_t)32768 * 256];
__device__ float g_o1c[(size_t)32768 * 256];
__device__ float g_o2r[(size_t)32768 * 256];
__device__ float g_o2c[(size_t)32768 * 256];

// ------------------------- 1) fold LN/BN into weights --------------------
__global__ void fold_w_kernel(const float* __restrict__ Wq1, const float* __restrict__ Wkv1,
                              const float* __restrict__ ln1q_w, const float* __restrict__ ln1kv_w,
                              const float* __restrict__ Wq2, const float* __restrict__ Wkv2,
                              const float* __restrict__ ln2q_w, const float* __restrict__ ln2kv_w,
                              const float* __restrict__ Wsc, const float* __restrict__ bn_gamma,
                              const float* __restrict__ bn_var) {
    int idx = blockIdx.x * 256 + threadIdx.x;
    if (idx < 384 * 768) {
        int c = idx / 768, j = idx % 768;
        g_Wbig1[idx] = (j < 256) ? ln1q_w[c] * Wq1[c * 256 + j]
                                 : ln1kv_w[c] * Wkv1[c * 512 + (j - 256)];
    }
    if (idx < 256 * 768) {
        int c = idx / 768, j = idx % 768;
        g_Wbig2[idx] = (j < 256) ? ln2q_w[c] * Wq2[c * 256 + j]
                                 : ln2kv_w[c] * Wkv2[c * 512 + (j - 256)];
    }
    if (idx < 384 * 256) {
        int c = idx / 256, o = idx % 256;
        float g = bn_gamma[o] * rsqrtf(bn_var[o] + EPSF);
        g_Wscf[idx] = Wsc[o * 384 + c] * g;
    }
}

__global__ __launch_bounds__(128)
void fold_cols_kernel(const float* __restrict__ Wq1, const float* __restrict__ Wkv1,
                      const float* __restrict__ ln1q_b, const float* __restrict__ ln1kv_b,
                      const float* __restrict__ Wq2, const float* __restrict__ Wkv2,
                      const float* __restrict__ ln2q_b, const float* __restrict__ ln2kv_b,
                      const float* __restrict__ bout1, const float* __restrict__ bout2,
                      const float* __restrict__ bn_gamma, const float* __restrict__ bn_beta,
                      const float* __restrict__ bn_mean, const float* __restrict__ bn_var) {
    int j = blockIdx.x;
    int t = threadIdx.x;
    float cs1 = 0.f, b1 = 0.f;
    for (int c = t; c < 384; c += 128) {
        cs1 += g_Wbig1[c * 768 + j];
        b1  += (j < 256) ? ln1q_b[c] * Wq1[c * 256 + j]
                         : ln1kv_b[c] * Wkv1[c * 512 + (j - 256)];
    }
    float cs2 = 0.f, b2 = 0.f;
    for (int c = t; c < 256; c += 128) {
        cs2 += g_Wbig2[c * 768 + j];
        b2  += (j < 256) ? ln2q_b[c] * Wq2[c * 256 + j]
                         : ln2kv_b[c] * Wkv2[c * 512 + (j - 256)];
    }
    __shared__ float red[4][128];
    red[0][t] = cs1; red[1][t] = b1; red[2][t] = cs2; red[3][t] = b2;
    __syncthreads();
#pragma unroll
    for (int s = 64; s > 0; s >>= 1) {
        if (t < s) {
#pragma unroll
            for (int v = 0; v < 4; v++) red[v][t] += red[v][t + s];
        }
        __syncthreads();
    }
    if (t == 0) {
        g_colsum1[j] = red[0][0];
        g_bb1[j]     = red[1][0];
        g_colsum2[j] = red[2][0];
        g_bb2[j]     = red[3][0];
        if (j < 256) {
            float g = bn_gamma[j] * rsqrtf(bn_var[j] + EPSF);
            g_btot[j] = (bn_beta[j] - bn_mean[j] * g) + bout1[j] + bout2[j];
        }
    }
}

// ------------------------- f32x2 micro-MMA, 8x16 thread tile -------------
__device__ __forceinline__ void mma16w(const u64 (*As)[66], const float (*Bs)[256],
                                       u64 (&acc)[8][8], int tx, int ty) {
#pragma unroll 4
    for (int kt = 0; kt < 16; kt++) {
        const ulonglong2* aq = (const ulonglong2*)&As[kt][ty * 8];
        ulonglong2 a01 = aq[0], a23 = aq[1], a45 = aq[2], a67 = aq[3];
        u64 a[8] = {a01.x, a01.y, a23.x, a23.y, a45.x, a45.y, a67.x, a67.y};
        u64 b[8];
#pragma unroll
        for (int q = 0; q < 4; q++) {
            ulonglong2 bv = *(const ulonglong2*)&Bs[kt][q * 64 + tx * 4];
            b[q * 2] = bv.x; b[q * 2 + 1] = bv.y;
        }
#pragma unroll
        for (int i = 0; i < 8; i++)
#pragma unroll
            for (int j = 0; j < 8; j++)
                acc[i][j] = fma2(a[i], b[j], acc[i][j]);
    }
}

// dynamic smem: Asd u64[2][16][66] @0 (16896 B), Bs float[2][16][256] @16896 (32768 B)
#define BS_OFF 16896
#define SMEM_GEMM_BYTES (16896 + 32768)

// ------------------------- 2) projection GEMM body -----------------------
template<int WHICH>
__device__ __forceinline__ void proj_body(const float* __restrict__ x) {
    constexpr int K = (WHICH == 0) ? 384 : 256;
    const float* __restrict__ Wf     = (WHICH == 0) ? g_Wbig1   : g_Wbig2;
    const float* __restrict__ colsum = (WHICH == 0) ? g_colsum1 : g_colsum2;
    const float* __restrict__ bb     = (WHICH == 0) ? g_bb1     : g_bb2;
    float* __restrict__ out          = (WHICH == 0) ? g_buf1    : g_buf2;

    extern __shared__ char smem[];
    u64 (*Asd)[16][66] = (u64(*)[16][66])smem;
    float (*Bs)[16][256] = (float(*)[16][256])(smem + BS_OFF);
    const uint32_t sbase = smem_u32(smem);

    const int tid = threadIdx.x;
    const int tx = tid & 15, ty = tid >> 4;
    const int s0 = blockIdx.y * 64;
    const int j0 = blockIdx.x * 256;
    const int b = s0 >> 12, p0 = s0 & 4095;
    const float* xb = x + ((size_t)b * K) * 4096 + p0;

    const int kA0 = tid >> 4, fA = tid & 15;
    const int kA1 = kA0 + 8;

    u64 acc[8][8];
#pragma unroll
    for (int i = 0; i < 8; i++)
#pragma unroll
        for (int j = 0; j < 8; j++) acc[i][j] = 0ULL;

    float asum[4] = {0.f, 0.f, 0.f, 0.f};
    float asq[4]  = {0.f, 0.f, 0.f, 0.f};

    float4 pa0, pa1;
    pa0 = *(const float4*)(xb + (size_t)kA0 * 4096 + fA * 4);
    pa1 = *(const float4*)(xb + (size_t)kA1 * 4096 + fA * 4);
#pragma unroll
    for (int i = 0; i < 8; i++) {
        int g = tid + i * 128;
        int kB = g >> 6, cB = g & 63;
        cp_async16(sbase + BS_OFF + kB * 1024 + cB * 16,
                   Wf + (size_t)kB * 768 + j0 + cB * 4);
    }
    CP_COMMIT();
    asum[0] += pa0.x + pa1.x; asq[0] += pa0.x * pa0.x + pa1.x * pa1.x;
    asum[1] += pa0.y + pa1.y; asq[1] += pa0.y * pa0.y + pa1.y * pa1.y;
    asum[2] += pa0.z + pa1.z; asq[2] += pa0.z * pa0.z + pa1.z * pa1.z;
    asum[3] += pa0.w + pa1.w; asq[3] += pa0.w * pa0.w + pa1.w * pa1.w;
    {
        float* d0 = (float*)&Asd[0][kA0][fA * 4];
        *(float4*)d0       = make_float4(pa0.x, pa0.x, pa0.y, pa0.y);
        *(float4*)(d0 + 4) = make_float4(pa0.z, pa0.z, pa0.w, pa0.w);
        float* d1 = (float*)&Asd[0][kA1][fA * 4];
        *(float4*)d1       = make_float4(pa1.x, pa1.x, pa1.y, pa1.y);
        *(float4*)(d1 + 4) = make_float4(pa1.z, pa1.z, pa1.w, pa1.w);
    }

    int buf = 0;
    for (int c0 = 0; c0 < K; c0 += 16, buf ^= 1) {
        CP_WAIT0();
        __syncthreads();
        bool has_next = (c0 + 16 < K);
        if (has_next) {
            const float* xn = xb + (size_t)(c0 + 16) * 4096;
            pa0 = *(const float4*)(xn + (size_t)kA0 * 4096 + fA * 4);
            pa1 = *(const float4*)(xn + (size_t)kA1 * 4096 + fA * 4);
            uint32_t bdst = sbase + BS_OFF + (buf ^ 1) * 16384;
            const float* wn = Wf + (size_t)(c0 + 16) * 768 + j0;
#pragma unroll
            for (int i = 0; i < 8; i++) {
                int g = tid + i * 128;
                int kB = g >> 6, cB = g & 63;
                cp_async16(bdst + kB * 1024 + cB * 16, wn + (size_t)kB * 768 + cB * 4);
            }
            CP_COMMIT();
        }
        mma16w(Asd[buf], Bs[buf], acc, tx, ty);
        if (has_next) {
            asum[0] += pa0.x + pa1.x; asq[0] += pa0.x * pa0.x + pa1.x * pa1.x;
            asum[1] += pa0.y + pa1.y; asq[1] += pa0.y * pa0.y + pa1.y * pa1.y;
            asum[2] += pa0.z + pa1.z; asq[2] += pa0.z * pa0.z + pa1.z * pa1.z;
            asum[3] += pa0.w + pa1.w; asq[3] += pa0.w * pa0.w + pa1.w * pa1.w;
            float* d0 = (float*)&Asd[buf ^ 1][kA0][fA * 4];
            *(float4*)d0       = make_float4(pa0.x, pa0.x, pa0.y, pa0.y);
            *(float4*)(d0 + 4) = make_float4(pa0.z, pa0.z, pa0.w, pa0.w);
            float* d1 = (float*)&Asd[buf ^ 1][kA1][fA * 4];
            *(float4*)d1       = make_float4(pa1.x, pa1.x, pa1.y, pa1.y);
            *(float4*)(d1 + 4) = make_float4(pa1.z, pa1.z, pa1.w, pa1.w);
        }
    }

    // ---- cross-thread LN-stat reduction through (now idle) smem ----
    __syncthreads();
    float* ps  = (float*)smem;          // [8][64]
    float* pq  = ps + 512;              // [8][64]
    float* muS = pq + 512;              // [64]
    float* rsS = muS + 64;              // [64]
#pragma unroll
    for (int i = 0; i < 4; i++) {
        ps[kA0 * 64 + fA * 4 + i] = asum[i];
        pq[kA0 * 64 + fA * 4 + i] = asq[i];
    }
    __syncthreads();
    if (tid < 64) {
        float s = 0.f, q = 0.f;
#pragma unroll
        for (int r = 0; r < 8; r++) {
            s += ps[r * 64 + tid];
            q += pq[r * 64 + tid];
        }
        float m = s * (1.0f / K);
        float v = q * (1.0f / K) - m * m;
        muS[tid] = m;
        rsS[tid] = rsqrtf(v + EPSF);
    }
    __syncthreads();

#pragma unroll
    for (int i = 0; i < 8; i++) {
        int srow = ty * 8 + i;
        int s = s0 + srow;
        float r = rsS[srow], m = muS[srow];
#pragma unroll
        for (int q = 0; q < 4; q++) {
            int jb = j0 + q * 64 + tx * 4;
            float4 cs = *(const float4*)(colsum + jb);
            float4 bv = *(const float4*)(bb + jb);
            float c0f, c1f, c2f, c3f;
            upk(acc[i][q * 2],     c0f, c1f);
            upk(acc[i][q * 2 + 1], c2f, c3f);
            float4 o;
            o.x = r * (c0f - m * cs.x) + bv.x;
            o.y = r * (c1f - m * cs.y) + bv.y;
            o.z = r * (c2f - m * cs.z) + bv.z;
            o.w = r * (c3f - m * cs.w) + bv.w;
            *(float4*)(out + (size_t)s * 768 + jb) = o;
        }
    }
}

// unified projection launch: z = 0 -> branch 1 (K=384, x1), z = 1 -> branch 2
__global__ __launch_bounds__(128, 2)
void proj_both_kernel(const float* __restrict__ x1, const float* __restrict__ x2) {
    if (blockIdx.z == 0) proj_body<0>(x1);
    else                 proj_body<1>(x2);
}

// ------------------------- 3) axial attention ----------------------------
// 64 threads = 2 warps; warp w handles head np*2+w; lane l handles queries
// 2l, 2l+1. Online softmax over 4 chunks of 16 keys. Each K/V broadcast row
// now feeds 2 queries (halved smem traffic per flop).
__global__ __launch_bounds__(64)
void attn_kernel() {
    __shared__ __align__(16) float Ks[2][64][32];
    __shared__ __align__(16) float Vs[2][64][32];
    const int t = threadIdx.x;
    const int w = t >> 5, l = t & 31;
    const int line = blockIdx.x;
    const int b = blockIdx.y >> 2, np = blockIdx.y & 3;
    const int n = np * 2 + w;
    const int br = blockIdx.z >> 1, dir = blockIdx.z & 1;

    const float* Qb  = br ? g_buf2 : g_buf1;
    const float* KVb = br ? g_buf1 : g_buf2;
    float* ob = br ? (dir ? g_o2c : g_o2r) : (dir ? g_o1c : g_o1r);

    // stage this warp's head K/V: lane l loads rows 2l, 2l+1
#pragma unroll
    for (int r = 0; r < 2; r++) {
        int j = 2 * l + r;
        int s_j = (dir == 0) ? (b * 4096 + j * 64 + line) : (b * 4096 + line * 64 + j);
        const float* kp = KVb + (size_t)s_j * 768 + 256 + n * 32;
        const float* vp = kp + 256;
#pragma unroll
        for (int d4 = 0; d4 < 8; d4++) {
            *(float4*)&Ks[w][j][d4 * 4] = *(const float4*)(kp + d4 * 4);
            *(float4*)&Vs[w][j][d4 * 4] = *(const float4*)(vp + d4 * 4);
        }
    }
    // load this lane's 2 queries
    u64 q20[16], q21[16];
    int sq0, sq1;
    {
        int qi0 = 2 * l, qi1 = 2 * l + 1;
        sq0 = (dir == 0) ? (b * 4096 + qi0 * 64 + line) : (b * 4096 + line * 64 + qi0);
        sq1 = (dir == 0) ? (b * 4096 + qi1 * 64 + line) : (b * 4096 + line * 64 + qi1);
        const float* qp0 = Qb + (size_t)sq0 * 768 + n * 32;
        const float* qp1 = Qb + (size_t)sq1 * 768 + n * 32;
#pragma unroll
        for (int d = 0; d < 16; d++) {
            q20[d] = *(const u64*)(qp0 + 2 * d);
            q21[d] = *(const u64*)(qp1 + 2 * d);
        }
    }
    __syncwarp();   // warps are independent: warp-local smem producer/consumer

    const float SC = 0.17677669529663687f;   // 1/sqrt(32)
    float m0 = -1e30f, m1 = -1e30f, l0 = 0.f, l1 = 0.f;
    u64 o0[16], o1[16];
#pragma unroll
    for (int d = 0; d < 16; d++) { o0[d] = 0ULL; o1[d] = 0ULL; }

#pragma unroll
    for (int c = 0; c < 4; c++) {
        float cs0[16], cs1[16];
        float cm0 = -1e30f, cm1 = -1e30f;
#pragma unroll
        for (int jj = 0; jj < 16; jj++) {
            const u64* k2 = (const u64*)Ks[w][c * 16 + jj];
            u64 a0 = 0ULL, a1 = 0ULL;
#pragma unroll
            for (int d = 0; d < 16; d++) {
                a0 = fma2(q20[d], k2[d], a0);
                a1 = fma2(q21[d], k2[d], a1);
            }
            float x0, y0, x1, y1;
            upk(a0, x0, y0); upk(a1, x1, y1);
            float s0 = (x0 + y0) * SC, s1 = (x1 + y1) * SC;
            cs0[jj] = s0; cs1[jj] = s1;
            cm0 = fmaxf(cm0, s0); cm1 = fmaxf(cm1, s1);
        }
        float mn0 = fmaxf(m0, cm0), mn1 = fmaxf(m1, cm1);
        float cr0 = __expf(m0 - mn0), cr1 = __expf(m1 - mn1);
        l0 *= cr0; l1 *= cr1;
        u64 c0d = dupf(cr0), c1d = dupf(cr1);
#pragma unroll
        for (int d = 0; d < 16; d++) {
            o0[d] = fma2(o0[d], c0d, 0ULL);
            o1[d] = fma2(o1[d], c1d, 0ULL);
        }
#pragma unroll
        for (int jj = 0; jj < 16; jj++) {
            const u64* v2 = (const u64*)Vs[w][c * 16 + jj];
            float p0 = __expf(cs0[jj] - mn0), p1 = __expf(cs1[jj] - mn1);
            l0 += p0; l1 += p1;
            u64 p0d = dupf(p0), p1d = dupf(p1);
#pragma unroll
            for (int d = 0; d < 16; d++) {
                o0[d] = fma2(p0d, v2[d], o0[d]);
                o1[d] = fma2(p1d, v2[d], o1[d]);
            }
        }
        m0 = mn0; m1 = mn1;
    }

    u64 i0 = dupf(1.f / l0), i1 = dupf(1.f / l1);
    float* op0 = ob + (size_t)sq0 * 256 + n * 32;
    float* op1 = ob + (size_t)sq1 * 256 + n * 32;
#pragma unroll
    for (int d = 0; d < 16; d++) {
        *(u64*)(op0 + 2 * d) = fma2(o0[d], i0, 0ULL);
        *(u64*)(op1 + 2 * d) = fma2(o1[d], i1, 0ULL);
    }
}

// ------------------------- 4) final fused GEMM ---------------------------
__global__ __launch_bounds__(128, 2)
void final_gemm_kernel(const float* __restrict__ x1, const float* __restrict__ x2,
                       const float* __restrict__ Wout1, const float* __restrict__ Wout2,
                       float* __restrict__ out) {
    extern __shared__ char smem[];
    u64 (*Asd)[16][66] = (u64(*)[16][66])smem;
    float (*Bs)[16][256] = (float(*)[16][256])(smem + BS_OFF);
    const uint32_t sbase = smem_u32(smem);

    const int tid = threadIdx.x;
    const int tx = tid & 15, ty = tid >> 4;
    const int s0 = blockIdx.x * 64;
    const int b = s0 >> 12, p0 = s0 & 4095;

    const int kA0 = tid >> 4, fA = tid & 15;
    const int kA1 = kA0 + 8;

    u64 acc[8][8];
#pragma unroll
    for (int i = 0; i < 8; i++)
#pragma unroll
        for (int j = 0; j < 8; j++) acc[i][j] = 0ULL;

    int buf = 0;

    // ---------- Phase A: shortcut conv (x1 c-major @ g_Wscf), K = 384 ----
    {
        const float* xb = x1 + ((size_t)b * 384) * 4096 + p0;
        float4 pa0, pa1;
        pa0 = *(const float4*)(xb + (size_t)kA0 * 4096 + fA * 4);
        pa1 = *(const float4*)(xb + (size_t)kA1 * 4096 + fA * 4);
#pragma unroll
        for (int i = 0; i < 8; i++) {
            int g = tid + i * 128;
            int kB = g >> 6, cB = g & 63;
            cp_async16(sbase + BS_OFF + buf * 16384 + kB * 1024 + cB * 16,
                       g_Wscf + (size_t)kB * 256 + cB * 4);
        }
        CP_COMMIT();
        {
            float* d0 = (float*)&Asd[buf][kA0][fA * 4];
            *(float4*)d0       = make_float4(pa0.x, pa0.x, pa0.y, pa0.y);
            *(float4*)(d0 + 4) = make_float4(pa0.z, pa0.z, pa0.w, pa0.w);
            float* d1 = (float*)&Asd[buf][kA1][fA * 4];
            *(float4*)d1       = make_float4(pa1.x, pa1.x, pa1.y, pa1.y);
            *(float4*)(d1 + 4) = make_float4(pa1.z, pa1.z, pa1.w, pa1.w);
        }
        for (int c0 = 0; c0 < 384; c0 += 16, buf ^= 1) {
            CP_WAIT0();
            __syncthreads();
            bool has_next = (c0 + 16 < 384);
            if (has_next) {
                const float* xn = xb + (size_t)(c0 + 16) * 4096;
                pa0 = *(const float4*)(xn + (size_t)kA0 * 4096 + fA * 4);
                pa1 = *(const float4*)(xn + (size_t)kA1 * 4096 + fA * 4);
                uint32_t bdst = sbase + BS_OFF + (buf ^ 1) * 16384;
                const float* wn = g_Wscf + (size_t)(c0 + 16) * 256;
#pragma unroll
                for (int i = 0; i < 8; i++) {
                    int g = tid + i * 128;
                    int kB = g >> 6, cB = g & 63;
                    cp_async16(bdst + kB * 1024 + cB * 16, wn + (size_t)kB * 256 + cB * 4);
                }
                CP_COMMIT();
            }
            mma16w(Asd[buf], Bs[buf], acc, tx, ty);
            if (has_next) {
                float* d0 = (float*)&Asd[buf ^ 1][kA0][fA * 4];
                *(float4*)d0       = make_float4(pa0.x, pa0.x, pa0.y, pa0.y);
                *(float4*)(d0 + 4) = make_float4(pa0.z, pa0.z, pa0.w, pa0.w);
                float* d1 = (float*)&Asd[buf ^ 1][kA1][fA * 4];
                *(float4*)d1       = make_float4(pa1.x, pa1.x, pa1.y, pa1.y);
                *(float4*)(d1 + 4) = make_float4(pa1.z, pa1.z, pa1.w, pa1.w);
            }
        }
    }

    // ---------- Phases B/C: (o_r + o_c) @ Wout, K = 256 each -------------
    const int rowA0 = tid >> 2, qA0 = tid & 3;
    const int rowA1 = (tid + 128) >> 2, qA1 = (tid + 128) & 3;
#pragma unroll
    for (int ph = 0; ph < 2; ph++) {
        const float* o_r = ph ? g_o2r : g_o1r;
        const float* o_c = ph ? g_o2c : g_o1c;
        const float* W   = ph ? Wout2 : Wout1;

        float4 sa0, sa1;
        {
            float4 a = *(const float4*)(o_r + (size_t)(s0 + rowA0) * 256 + qA0 * 4);
            float4 c = *(const float4*)(o_c + (size_t)(s0 + rowA0) * 256 + qA0 * 4);
            sa0 = make_float4(a.x + c.x, a.y + c.y, a.z + c.z, a.w + c.w);
            a = *(const float4*)(o_r + (size_t)(s0 + rowA1) * 256 + qA1 * 4);
            c = *(const float4*)(o_c + (size_t)(s0 + rowA1) * 256 + qA1 * 4);
            sa1 = make_float4(a.x + c.x, a.y + c.y, a.z + c.z, a.w + c.w);
        }
        __syncthreads();  // previous phase readers done before overwriting buf
#pragma unroll
        for (int i = 0; i < 8; i++) {
            int g = tid + i * 128;
            int kB = g >> 6, cB = g & 63;
            cp_async16(sbase + BS_OFF + buf * 16384 + kB * 1024 + cB * 16,
                       W + (size_t)kB * 256 + cB * 4);
        }
        CP_COMMIT();
        {
            Asd[buf][qA0 * 4 + 0][rowA0] = dupf(sa0.x);
            Asd[buf][qA0 * 4 + 1][rowA0] = dupf(sa0.y);
            Asd[buf][qA0 * 4 + 2][rowA0] = dupf(sa0.z);
            Asd[buf][qA0 * 4 + 3][rowA0] = dupf(sa0.w);
            Asd[buf][qA1 * 4 + 0][rowA1] = dupf(sa1.x);
            Asd[buf][qA1 * 4 + 1][rowA1] = dupf(sa1.y);
            Asd[buf][qA1 * 4 + 2][rowA1] = dupf(sa1.z);
            Asd[buf][qA1 * 4 + 3][rowA1] = dupf(sa1.w);
        }
        for (int c0 = 0; c0 < 256; c0 += 16, buf ^= 1) {
            CP_WAIT0();
            __syncthreads();
            bool has_next = (c0 + 16 < 256);
            if (has_next) {
                int cn = c0 + 16;
                float4 a = *(const float4*)(o_r + (size_t)(s0 + rowA0) * 256 + cn + qA0 * 4);
                float4 c = *(const float4*)(o_c + (size_t)(s0 + rowA0) * 256 + cn + qA0 * 4);
                sa0 = make_float4(a.x + c.x, a.y + c.y, a.z + c.z, a.w + c.w);
                a = *(const float4*)(o_r + (size_t)(s0 + rowA1) * 256 + cn + qA1 * 4);
                c = *(const float4*)(o_c + (size_t)(s0 + rowA1) * 256 + cn + qA1 * 4);
                sa1 = make_float4(a.x + c.x, a.y + c.y, a.z + c.z, a.w + c.w);
                uint32_t bdst = sbase + BS_OFF + (buf ^ 1) * 16384;
                const float* wn = W + (size_t)cn * 256;
#pragma unroll
                for (int i = 0; i < 8; i++) {
                    int g = tid + i * 128;
                    int kB = g >> 6, cB = g & 63;
                    cp_async16(bdst + kB * 1024 + cB * 16, wn + (size_t)kB * 256 + cB * 4);
                }
                CP_COMMIT();
            }
            mma16w(Asd[buf], Bs[buf], acc, tx, ty);
            if (has_next) {
                Asd[buf ^ 1][qA0 * 4 + 0][rowA0] = dupf(sa0.x);
                Asd[buf ^ 1][qA0 * 4 + 1][rowA0] = dupf(sa0.y);
                Asd[buf ^ 1][qA0 * 4 + 2][rowA0] = dupf(sa0.z);
                Asd[buf ^ 1][qA0 * 4 + 3][rowA0] = dupf(sa0.w);
                Asd[buf ^ 1][qA1 * 4 + 0][rowA1] = dupf(sa1.x);
                Asd[buf ^ 1][qA1 * 4 + 1][rowA1] = dupf(sa1.y);
                Asd[buf ^ 1][qA1 * 4 + 2][rowA1] = dupf(sa1.z);
                Asd[buf ^ 1][qA1 * 4 + 3][rowA1] = dupf(sa1.w);
            }
        }
    }

    // epilogue: bias + x2 residual, store NCHW (cols = q*64 + tx*4 + c)
    float cf[8][16];
#pragma unroll
    for (int i = 0; i < 8; i++)
#pragma unroll
        for (int j = 0; j < 8; j++)
            upk(acc[i][j], cf[i][2 * j], cf[i][2 * j + 1]);

#pragma unroll
    for (int q = 0; q < 4; q++) {
#pragma unroll
        for (int c = 0; c < 4; c++) {
            int o = q * 64 + tx * 4 + c;
            int lcol = q * 4 + c;
            size_t base = ((size_t)(b * 256 + o)) * 4096 + p0 + ty * 8;
            float bt = g_btot[o];
            float4 xa  = *(const float4*)(x2 + base);
            float4 xb4 = *(const float4*)(x2 + base + 4);
            float4 r0, r1;
            r0.x = cf[0][lcol] + bt + xa.x;
            r0.y = cf[1][lcol] + bt + xa.y;
            r0.z = cf[2][lcol] + bt + xa.z;
            r0.w = cf[3][lcol] + bt + xa.w;
            r1.x = cf[4][lcol] + bt + xb4.x;
            r1.y = cf[5][lcol] + bt + xb4.y;
            r1.z = cf[6][lcol] + bt + xb4.z;
            r1.w = cf[7][lcol] + bt + xb4.w;
            *(float4*)(out + base) = r0;
            *(float4*)(out + base + 4) = r1;
        }
    }
}

// ------------------------- launch ---------------------------------------
extern "C" void kernel_launch(void* const* d_in, const int* in_sizes, int n_in,
                              void* d_out, int out_size) {
    (void)in_sizes; (void)n_in; (void)out_size;
    const float* x1      = (const float*)d_in[0];
    const float* x2      = (const float*)d_in[1];
    const float* ln1q_w  = (const float*)d_in[2];
    const float* ln1q_b  = (const float*)d_in[3];
    const float* ln2kv_w = (const float*)d_in[4];
    const float* ln2kv_b = (const float*)d_in[5];
    const float* Wq1     = (const float*)d_in[6];
    const float* Wkv2    = (const float*)d_in[7];
    const float* Wout1   = (const float*)d_in[8];
    const float* bout1   = (const float*)d_in[9];
    const float* ln2q_w  = (const float*)d_in[10];
    const float* ln2q_b  = (const float*)d_in[11];
    const float* ln1kv_w = (const float*)d_in[12];
    const float* ln1kv_b = (const float*)d_in[13];
    const float* Wq2     = (const float*)d_in[14];
    const float* Wkv1    = (const float*)d_in[15];
    const float* Wout2   = (const float*)d_in[16];
    const float* bout2   = (const float*)d_in[17];
    const float* Wsc     = (const float*)d_in[18];
    const float* bn_g    = (const float*)d_in[19];
    const float* bn_b    = (const float*)d_in[20];
    const float* bn_m    = (const float*)d_in[21];
    const float* bn_v    = (const float*)d_in[22];
    float* out = (float*)d_out;

    cudaFuncSetAttribute(proj_both_kernel, cudaFuncAttributeMaxDynamicSharedMemorySize, SMEM_GEMM_BYTES);
    cudaFuncSetAttribute(final_gemm_kernel, cudaFuncAttributeMaxDynamicSharedMemorySize, SMEM_GEMM_BYTES);

    fold_w_kernel<<<1152, 256>>>(Wq1, Wkv1, ln1q_w, ln1kv_w,
                                 Wq2, Wkv2, ln2q_w, ln2kv_w,
                                 Wsc, bn_g, bn_v);
    fold_cols_kernel<<<768, 128>>>(Wq1, Wkv1, ln1q_b, ln1kv_b,
                                   Wq2, Wkv2, ln2q_b, ln2kv_b,
                                   bout1, bout2, bn_g, bn_b, bn_m, bn_v);
    proj_both_kernel<<<dim3(3, 512, 2), 128, SMEM_GEMM_BYTES>>>(x1, x2);
    attn_kernel<<<dim3(64, 32, 4), 64>>>();
    final_gemm_kernel<<<512, 128, SMEM_GEMM_BYTES>>>(x1, x2, Wout1, Wout2, out);
}

// round 17
// speedup vs baseline: 1.8821x; 1.1108x over previous
#include <cuda_runtime.h>
#include <cstdint>
#include <cstddef>

#define EPSF 1e-5f

typedef unsigned long long u64;

// ------------------------- packed f32x2 helpers -------------------------
__device__ __forceinline__ u64 pk(float lo, float hi) {
    u64 r; asm("mov.b64 %0, {%1, %2};" : "=l"(r) : "f"(lo), "f"(hi)); return r;
}
__device__ __forceinline__ u64 dupf(float v) { return pk(v, v); }
__device__ __forceinline__ u64 fma2(u64 a, u64 b, u64 c) {
    u64 d; asm("fma.rn.f32x2 %0, %1, %2, %3;" : "=l"(d) : "l"(a), "l"(b), "l"(c)); return d;
}
__device__ __forceinline__ void upk(u64 v, float& lo, float& hi) {
    asm("mov.b64 {%0, %1}, %2;" : "=f"(lo), "=f"(hi) : "l"(v));
}

// ------------------------- cp.async helpers ------------------------------
__device__ __forceinline__ uint32_t smem_u32(const void* p) {
    uint32_t a;
    asm("{ .reg .u64 t; cvta.to.shared.u64 t, %1; cvt.u32.u64 %0, t; }" : "=r"(a) : "l"(p));
    return a;
}
__device__ __forceinline__ void cp_async16(uint32_t dst, const void* src) {
    asm volatile("cp.async.cg.shared.global [%0], [%1], 16;" :: "r"(dst), "l"(src) : "memory");
}
#define CP_COMMIT() asm volatile("cp.async.commit_group;" ::: "memory")
#define CP_WAIT0()  asm volatile("cp.async.wait_group 0;" ::: "memory")

// ------------------------- scratch (static device) ----------------------
__device__ float g_Wbig1[384 * 768];
__device__ float g_Wbig2[256 * 768];
__device__ float g_Wscf[384 * 256];
__device__ float g_colsum1[768], g_bb1[768];
__device__ float g_colsum2[768], g_bb2[768];
__device__ float g_btot[256];
__device__ float g_buf1[(size_t)32768 * 768];
__device__ float g_buf2[(size_t)32768 * 768];
__device__ float g_o1r[(size_t)32768 * 256];
__device__ float g_o1c[(size_t)32768 * 256];
__device__ float g_o2r[(size_t)32768 * 256];
__device__ float g_o2c[(size_t)32768 * 256];

// ------------------------- 1) fold LN/BN into weights --------------------
__global__ void fold_w_kernel(const float* __restrict__ Wq1, const float* __restrict__ Wkv1,
                              const float* __restrict__ ln1q_w, const float* __restrict__ ln1kv_w,
                              const float* __restrict__ Wq2, const float* __restrict__ Wkv2,
                              const float* __restrict__ ln2q_w, const float* __restrict__ ln2kv_w,
                              const float* __restrict__ Wsc, const float* __restrict__ bn_gamma,
                              const float* __restrict__ bn_var) {
    int idx = blockIdx.x * 256 + threadIdx.x;
    if (idx < 384 * 768) {
        int c = idx / 768, j = idx % 768;
        g_Wbig1[idx] = (j < 256) ? ln1q_w[c] * Wq1[c * 256 + j]
                                 : ln1kv_w[c] * Wkv1[c * 512 + (j - 256)];
    }
    if (idx < 256 * 768) {
        int c = idx / 768, j = idx % 768;
        g_Wbig2[idx] = (j < 256) ? ln2q_w[c] * Wq2[c * 256 + j]
                                 : ln2kv_w[c] * Wkv2[c * 512 + (j - 256)];
    }
    if (idx < 384 * 256) {
        int c = idx / 256, o = idx % 256;
        float g = bn_gamma[o] * rsqrtf(bn_var[o] + EPSF);
        g_Wscf[idx] = Wsc[o * 384 + c] * g;
    }
}

__global__ __launch_bounds__(128)
void fold_cols_kernel(const float* __restrict__ Wq1, const float* __restrict__ Wkv1,
                      const float* __restrict__ ln1q_b, const float* __restrict__ ln1kv_b,
                      const float* __restrict__ Wq2, const float* __restrict__ Wkv2,
                      const float* __restrict__ ln2q_b, const float* __restrict__ ln2kv_b,
                      const float* __restrict__ bout1, const float* __restrict__ bout2,
                      const float* __restrict__ bn_gamma, const float* __restrict__ bn_beta,
                      const float* __restrict__ bn_mean, const float* __restrict__ bn_var) {
    int j = blockIdx.x;
    int t = threadIdx.x;
    float cs1 = 0.f, b1 = 0.f;
    for (int c = t; c < 384; c += 128) {
        cs1 += g_Wbig1[c * 768 + j];
        b1  += (j < 256) ? ln1q_b[c] * Wq1[c * 256 + j]
                         : ln1kv_b[c] * Wkv1[c * 512 + (j - 256)];
    }
    float cs2 = 0.f, b2 = 0.f;
    for (int c = t; c < 256; c += 128) {
        cs2 += g_Wbig2[c * 768 + j];
        b2  += (j < 256) ? ln2q_b[c] * Wq2[c * 256 + j]
                         : ln2kv_b[c] * Wkv2[c * 512 + (j - 256)];
    }
    __shared__ float red[4][128];
    red[0][t] = cs1; red[1][t] = b1; red[2][t] = cs2; red[3][t] = b2;
    __syncthreads();
#pragma unroll
    for (int s = 64; s > 0; s >>= 1) {
        if (t < s) {
#pragma unroll
            for (int v = 0; v < 4; v++) red[v][t] += red[v][t + s];
        }
        __syncthreads();
    }
    if (t == 0) {
        g_colsum1[j] = red[0][0];
        g_bb1[j]     = red[1][0];
        g_colsum2[j] = red[2][0];
        g_bb2[j]     = red[3][0];
        if (j < 256) {
            float g = bn_gamma[j] * rsqrtf(bn_var[j] + EPSF);
            g_btot[j] = (bn_beta[j] - bn_mean[j] * g) + bout1[j] + bout2[j];
        }
    }
}

// ------------------------- f32x2 micro-MMA, 8x16 thread tile -------------
__device__ __forceinline__ void mma16w(const u64 (*As)[66], const float (*Bs)[256],
                                       u64 (&acc)[8][8], int tx, int ty) {
#pragma unroll 4
    for (int kt = 0; kt < 16; kt++) {
        const ulonglong2* aq = (const ulonglong2*)&As[kt][ty * 8];
        ulonglong2 a01 = aq[0], a23 = aq[1], a45 = aq[2], a67 = aq[3];
        u64 a[8] = {a01.x, a01.y, a23.x, a23.y, a45.x, a45.y, a67.x, a67.y};
        u64 b[8];
#pragma unroll
        for (int q = 0; q < 4; q++) {
            ulonglong2 bv = *(const ulonglong2*)&Bs[kt][q * 64 + tx * 4];
            b[q * 2] = bv.x; b[q * 2 + 1] = bv.y;
        }
#pragma unroll
        for (int i = 0; i < 8; i++)
#pragma unroll
            for (int j = 0; j < 8; j++)
                acc[i][j] = fma2(a[i], b[j], acc[i][j]);
    }
}

// dynamic smem: Asd u64[2][16][66] @0 (16896 B), Bs float[2][16][256] @16896 (32768 B)
#define BS_OFF 16896
#define SMEM_GEMM_BYTES (16896 + 32768)

// ------------------------- 2) projection GEMM body -----------------------
template<int WHICH>
__device__ __forceinline__ void proj_body(const float* __restrict__ x) {
    constexpr int K = (WHICH == 0) ? 384 : 256;
    const float* __restrict__ Wf     = (WHICH == 0) ? g_Wbig1   : g_Wbig2;
    const float* __restrict__ colsum = (WHICH == 0) ? g_colsum1 : g_colsum2;
    const float* __restrict__ bb     = (WHICH == 0) ? g_bb1     : g_bb2;
    float* __restrict__ out          = (WHICH == 0) ? g_buf1    : g_buf2;

    extern __shared__ char smem[];
    u64 (*Asd)[16][66] = (u64(*)[16][66])smem;
    float (*Bs)[16][256] = (float(*)[16][256])(smem + BS_OFF);
    const uint32_t sbase = smem_u32(smem);

    const int tid = threadIdx.x;
    const int tx = tid & 15, ty = tid >> 4;
    const int s0 = blockIdx.y * 64;
    const int j0 = blockIdx.x * 256;
    const int b = s0 >> 12, p0 = s0 & 4095;
    const float* xb = x + ((size_t)b * K) * 4096 + p0;

    const int kA0 = tid >> 4, fA = tid & 15;
    const int kA1 = kA0 + 8;

    u64 acc[8][8];
#pragma unroll
    for (int i = 0; i < 8; i++)
#pragma unroll
        for (int j = 0; j < 8; j++) acc[i][j] = 0ULL;

    float asum[4] = {0.f, 0.f, 0.f, 0.f};
    float asq[4]  = {0.f, 0.f, 0.f, 0.f};

    float4 pa0, pa1;
    pa0 = *(const float4*)(xb + (size_t)kA0 * 4096 + fA * 4);
    pa1 = *(const float4*)(xb + (size_t)kA1 * 4096 + fA * 4);
#pragma unroll
    for (int i = 0; i < 8; i++) {
        int g = tid + i * 128;
        int kB = g >> 6, cB = g & 63;
        cp_async16(sbase + BS_OFF + kB * 1024 + cB * 16,
                   Wf + (size_t)kB * 768 + j0 + cB * 4);
    }
    CP_COMMIT();
    asum[0] += pa0.x + pa1.x; asq[0] += pa0.x * pa0.x + pa1.x * pa1.x;
    asum[1] += pa0.y + pa1.y; asq[1] += pa0.y * pa0.y + pa1.y * pa1.y;
    asum[2] += pa0.z + pa1.z; asq[2] += pa0.z * pa0.z + pa1.z * pa1.z;
    asum[3] += pa0.w + pa1.w; asq[3] += pa0.w * pa0.w + pa1.w * pa1.w;
    {
        float* d0 = (float*)&Asd[0][kA0][fA * 4];
        *(float4*)d0       = make_float4(pa0.x, pa0.x, pa0.y, pa0.y);
        *(float4*)(d0 + 4) = make_float4(pa0.z, pa0.z, pa0.w, pa0.w);
        float* d1 = (float*)&Asd[0][kA1][fA * 4];
        *(float4*)d1       = make_float4(pa1.x, pa1.x, pa1.y, pa1.y);
        *(float4*)(d1 + 4) = make_float4(pa1.z, pa1.z, pa1.w, pa1.w);
    }

    int buf = 0;
    for (int c0 = 0; c0 < K; c0 += 16, buf ^= 1) {
        CP_WAIT0();
        __syncthreads();
        bool has_next = (c0 + 16 < K);
        if (has_next) {
            const float* xn = xb + (size_t)(c0 + 16) * 4096;
            pa0 = *(const float4*)(xn + (size_t)kA0 * 4096 + fA * 4);
            pa1 = *(const float4*)(xn + (size_t)kA1 * 4096 + fA * 4);
            uint32_t bdst = sbase + BS_OFF + (buf ^ 1) * 16384;
            const float* wn = Wf + (size_t)(c0 + 16) * 768 + j0;
#pragma unroll
            for (int i = 0; i < 8; i++) {
                int g = tid + i * 128;
                int kB = g >> 6, cB = g & 63;
                cp_async16(bdst + kB * 1024 + cB * 16, wn + (size_t)kB * 768 + cB * 4);
            }
            CP_COMMIT();
        }
        mma16w(Asd[buf], Bs[buf], acc, tx, ty);
        if (has_next) {
            asum[0] += pa0.x + pa1.x; asq[0] += pa0.x * pa0.x + pa1.x * pa1.x;
            asum[1] += pa0.y + pa1.y; asq[1] += pa0.y * pa0.y + pa1.y * pa1.y;
            asum[2] += pa0.z + pa1.z; asq[2] += pa0.z * pa0.z + pa1.z * pa1.z;
            asum[3] += pa0.w + pa1.w; asq[3] += pa0.w * pa0.w + pa1.w * pa1.w;
            float* d0 = (float*)&Asd[buf ^ 1][kA0][fA * 4];
            *(float4*)d0       = make_float4(pa0.x, pa0.x, pa0.y, pa0.y);
            *(float4*)(d0 + 4) = make_float4(pa0.z, pa0.z, pa0.w, pa0.w);
            float* d1 = (float*)&Asd[buf ^ 1][kA1][fA * 4];
            *(float4*)d1       = make_float4(pa1.x, pa1.x, pa1.y, pa1.y);
            *(float4*)(d1 + 4) = make_float4(pa1.z, pa1.z, pa1.w, pa1.w);
        }
    }

    // ---- cross-thread LN-stat reduction through (now idle) smem ----
    __syncthreads();
    float* ps  = (float*)smem;          // [8][64]
    float* pq  = ps + 512;              // [8][64]
    float* muS = pq + 512;              // [64]
    float* rsS = muS + 64;              // [64]
#pragma unroll
    for (int i = 0; i < 4; i++) {
        ps[kA0 * 64 + fA * 4 + i] = asum[i];
        pq[kA0 * 64 + fA * 4 + i] = asq[i];
    }
    __syncthreads();
    if (tid < 64) {
        float s = 0.f, q = 0.f;
#pragma unroll
        for (int r = 0; r < 8; r++) {
            s += ps[r * 64 + tid];
            q += pq[r * 64 + tid];
        }
        float m = s * (1.0f / K);
        float v = q * (1.0f / K) - m * m;
        muS[tid] = m;
        rsS[tid] = rsqrtf(v + EPSF);
    }
    __syncthreads();

#pragma unroll
    for (int i = 0; i < 8; i++) {
        int srow = ty * 8 + i;
        int s = s0 + srow;
        float r = rsS[srow], m = muS[srow];
#pragma unroll
        for (int q = 0; q < 4; q++) {
            int jb = j0 + q * 64 + tx * 4;
            float4 cs = *(const float4*)(colsum + jb);
            float4 bv = *(const float4*)(bb + jb);
            float c0f, c1f, c2f, c3f;
            upk(acc[i][q * 2],     c0f, c1f);
            upk(acc[i][q * 2 + 1], c2f, c3f);
            float4 o;
            o.x = r * (c0f - m * cs.x) + bv.x;
            o.y = r * (c1f - m * cs.y) + bv.y;
            o.z = r * (c2f - m * cs.z) + bv.z;
            o.w = r * (c3f - m * cs.w) + bv.w;
            *(float4*)(out + (size_t)s * 768 + jb) = o;
        }
    }
}

// unified projection launch: z = 0 -> branch 1 (K=384, x1), z = 1 -> branch 2
__global__ __launch_bounds__(128, 2)
void proj_both_kernel(const float* __restrict__ x1, const float* __restrict__ x2) {
    if (blockIdx.z == 0) proj_body<0>(x1);
    else                 proj_body<1>(x2);
}

// ------------------------- 3) axial attention (GEMM-style) ----------------
// Block = 2 warps; warp w = head np*2+w of one (b, line, dir, branch).
// Phase 1: S^T[64k x 64q] = K·Q^T via register-tiled GEMM over d=32
//          (K^T, Q^T staged transposed in smem; non-broadcast reads).
// Phase 2: register softmax per q-column (shfl reductions), P^T written to
//          smem (overlay of K^T/Q^T, XOR-swizzled 16B granules).
// Phase 3: O[64q x 32d] = P^T·V GEMM (V staged via cp.async, natural rows).
__global__ __launch_bounds__(64, 4)
void attn_kernel() {
    __shared__ __align__(16) float KQ[2][2][32][64];  // [w][{K^T,Q^T}][d][slot]
    __shared__ __align__(16) float Vsm[2][64][32];
    const int t = threadIdx.x;
    const int w = t >> 5, l = t & 31;
    const int line = blockIdx.x;
    const int b = blockIdx.y >> 2, np = blockIdx.y & 3;
    const int n = np * 2 + w;
    const int br = blockIdx.z >> 1, dir = blockIdx.z & 1;

    const float* Qb  = br ? g_buf2 : g_buf1;
    const float* KVb = br ? g_buf1 : g_buf2;
    float* ob = br ? (dir ? g_o2c : g_o2r) : (dir ? g_o1c : g_o1r);

    // ---- stage: lane l handles rows 2l, 2l+1 ----
#pragma unroll
    for (int r = 0; r < 2; r++) {
        int k = 2 * l + r;
        int sk = (dir == 0) ? (b * 4096 + k * 64 + line) : (b * 4096 + line * 64 + k);
        const float* qp = Qb  + (size_t)sk * 768 + n * 32;
        const float* kp = KVb + (size_t)sk * 768 + 256 + n * 32;
        const float* vp = kp + 256;
#pragma unroll
        for (int d4 = 0; d4 < 8; d4++) {
            float4 kv = *(const float4*)(kp + d4 * 4);
            KQ[w][0][d4 * 4 + 0][k] = kv.x;
            KQ[w][0][d4 * 4 + 1][k] = kv.y;
            KQ[w][0][d4 * 4 + 2][k] = kv.z;
            KQ[w][0][d4 * 4 + 3][k] = kv.w;
            float4 qv = *(const float4*)(qp + d4 * 4);
            KQ[w][1][d4 * 4 + 0][k] = qv.x;
            KQ[w][1][d4 * 4 + 1][k] = qv.y;
            KQ[w][1][d4 * 4 + 2][k] = qv.z;
            KQ[w][1][d4 * 4 + 3][k] = qv.w;
        }
        uint32_t vdst = smem_u32(&Vsm[w][k][0]);
#pragma unroll
        for (int g = 0; g < 8; g++) cp_async16(vdst + g * 16, vp + g * 4);
    }
    CP_COMMIT();
    __syncwarp();

    const int ty = l >> 2, tx = l & 3;   // k-rows = ty*8.. ; q-cols = tx*16..

    // ---- Phase 1: S^T GEMM ----
    u64 acc[8][8];
#pragma unroll
    for (int i = 0; i < 8; i++)
#pragma unroll
        for (int j = 0; j < 8; j++) acc[i][j] = 0ULL;

#pragma unroll 4
    for (int kt = 0; kt < 32; kt++) {
        float4 a0 = *(const float4*)&KQ[w][0][kt][ty * 8];
        float4 a1 = *(const float4*)&KQ[w][0][kt][ty * 8 + 4];
        float af[8] = {a0.x, a0.y, a0.z, a0.w, a1.x, a1.y, a1.z, a1.w};
        const ulonglong2* bq = (const ulonglong2*)&KQ[w][1][kt][tx * 16];
        ulonglong2 b01 = bq[0], b23 = bq[1], b45 = bq[2], b67 = bq[3];
        u64 bb[8] = {b01.x, b01.y, b23.x, b23.y, b45.x, b45.y, b67.x, b67.y};
#pragma unroll
        for (int i = 0; i < 8; i++) {
            u64 ad = dupf(af[i]);
#pragma unroll
            for (int j = 0; j < 8; j++)
                acc[i][j] = fma2(ad, bb[j], acc[i][j]);
        }
    }

    // ---- Phase 2: softmax per q-column ----
    const float SC = 0.17677669529663687f;   // 1/sqrt(32)
    float S[8][16];
#pragma unroll
    for (int i = 0; i < 8; i++)
#pragma unroll
        for (int j = 0; j < 8; j++) {
            float lo, hi; upk(acc[i][j], lo, hi);
            S[i][2 * j] = lo * SC;
            S[i][2 * j + 1] = hi * SC;
        }

    float inv[16];
#pragma unroll
    for (int q = 0; q < 16; q++) {
        float m = S[0][q];
#pragma unroll
        for (int i = 1; i < 8; i++) m = fmaxf(m, S[i][q]);
        m = fmaxf(m, __shfl_xor_sync(0xffffffffu, m, 4));
        m = fmaxf(m, __shfl_xor_sync(0xffffffffu, m, 8));
        m = fmaxf(m, __shfl_xor_sync(0xffffffffu, m, 16));
        float s = 0.f;
#pragma unroll
        for (int i = 0; i < 8; i++) {
            float e = __expf(S[i][q] - m);
            S[i][q] = e;
            s += e;
        }
        s += __shfl_xor_sync(0xffffffffu, s, 4);
        s += __shfl_xor_sync(0xffffffffu, s, 8);
        s += __shfl_xor_sync(0xffffffffu, s, 16);
        inv[q] = 1.f / s;
    }

    __syncwarp();   // all K^T/Q^T reads done before overlay write
    float* Pt = &KQ[w][0][0][0];   // 64 x 64 overlay, XOR-swizzled granules
#pragma unroll
    for (int i = 0; i < 8; i++) {
        int k = ty * 8 + i;
#pragma unroll
        for (int c = 0; c < 4; c++) {
            int g = tx * 4 + c;
            int gp = g ^ ty;            // swizzle by k>>3 (= ty)
            *(float4*)(Pt + k * 64 + gp * 4) =
                make_float4(S[i][c * 4 + 0] * inv[c * 4 + 0],
                            S[i][c * 4 + 1] * inv[c * 4 + 1],
                            S[i][c * 4 + 2] * inv[c * 4 + 2],
                            S[i][c * 4 + 3] * inv[c * 4 + 3]);
        }
    }
    CP_WAIT0();
    __syncwarp();

    // ---- Phase 3: O = P^T · V GEMM ----  (q-rows = ty*8.. ; d = tx*8..)
    u64 acc2[8][4];
#pragma unroll
    for (int i = 0; i < 8; i++)
#pragma unroll
        for (int j = 0; j < 4; j++) acc2[i][j] = 0ULL;

#pragma unroll 4
    for (int kt = 0; kt < 64; kt++) {
        int sw = kt >> 3;
        int g0 = (ty * 2 + 0) ^ sw;
        int g1 = (ty * 2 + 1) ^ sw;
        float4 pa0 = *(const float4*)(Pt + kt * 64 + g0 * 4);
        float4 pa1 = *(const float4*)(Pt + kt * 64 + g1 * 4);
        float af[8] = {pa0.x, pa0.y, pa0.z, pa0.w, pa1.x, pa1.y, pa1.z, pa1.w};
        const ulonglong2* vq = (const ulonglong2*)&Vsm[w][kt][tx * 8];
        ulonglong2 v01 = vq[0], v23 = vq[1];
        u64 vb[4] = {v01.x, v01.y, v23.x, v23.y};
#pragma unroll
        for (int i = 0; i < 8; i++) {
            u64 ad = dupf(af[i]);
#pragma unroll
            for (int j = 0; j < 4; j++)
                acc2[i][j] = fma2(ad, vb[j], acc2[i][j]);
        }
    }

    // ---- store O ----
#pragma unroll
    for (int i = 0; i < 8; i++) {
        int q = ty * 8 + i;
        int sq = (dir == 0) ? (b * 4096 + q * 64 + line) : (b * 4096 + line * 64 + q);
        float* op = ob + (size_t)sq * 256 + n * 32 + tx * 8;
        ulonglong2 r0; r0.x = acc2[i][0]; r0.y = acc2[i][1];
        ulonglong2 r1; r1.x = acc2[i][2]; r1.y = acc2[i][3];
        *(ulonglong2*)op = r0;
        *(ulonglong2*)(op + 4) = r1;
    }
}

// ------------------------- 4) final fused GEMM ---------------------------
__global__ __launch_bounds__(128, 2)
void final_gemm_kernel(const float* __restrict__ x1, const float* __restrict__ x2,
                       const float* __restrict__ Wout1, const float* __restrict__ Wout2,
                       float* __restrict__ out) {
    extern __shared__ char smem[];
    u64 (*Asd)[16][66] = (u64(*)[16][66])smem;
    float (*Bs)[16][256] = (float(*)[16][256])(smem + BS_OFF);
    const uint32_t sbase = smem_u32(smem);

    const int tid = threadIdx.x;
    const int tx = tid & 15, ty = tid >> 4;
    const int s0 = blockIdx.x * 64;
    const int b = s0 >> 12, p0 = s0 & 4095;

    const int kA0 = tid >> 4, fA = tid & 15;
    const int kA1 = kA0 + 8;

    u64 acc[8][8];
#pragma unroll
    for (int i = 0; i < 8; i++)
#pragma unroll
        for (int j = 0; j < 8; j++) acc[i][j] = 0ULL;

    int buf = 0;

    // ---------- Phase A: shortcut conv (x1 c-major @ g_Wscf), K = 384 ----
    {
        const float* xb = x1 + ((size_t)b * 384) * 4096 + p0;
        float4 pa0, pa1;
        pa0 = *(const float4*)(xb + (size_t)kA0 * 4096 + fA * 4);
        pa1 = *(const float4*)(xb + (size_t)kA1 * 4096 + fA * 4);
#pragma unroll
        for (int i = 0; i < 8; i++) {
            int g = tid + i * 128;
            int kB = g >> 6, cB = g & 63;
            cp_async16(sbase + BS_OFF + buf * 16384 + kB * 1024 + cB * 16,
                       g_Wscf + (size_t)kB * 256 + cB * 4);
        }
        CP_COMMIT();
        {
            float* d0 = (float*)&Asd[buf][kA0][fA * 4];
            *(float4*)d0       = make_float4(pa0.x, pa0.x, pa0.y, pa0.y);
            *(float4*)(d0 + 4) = make_float4(pa0.z, pa0.z, pa0.w, pa0.w);
            float* d1 = (float*)&Asd[buf][kA1][fA * 4];
            *(float4*)d1       = make_float4(pa1.x, pa1.x, pa1.y, pa1.y);
            *(float4*)(d1 + 4) = make_float4(pa1.z, pa1.z, pa1.w, pa1.w);
        }
        for (int c0 = 0; c0 < 384; c0 += 16, buf ^= 1) {
            CP_WAIT0();
            __syncthreads();
            bool has_next = (c0 + 16 < 384);
            if (has_next) {
                const float* xn = xb + (size_t)(c0 + 16) * 4096;
                pa0 = *(const float4*)(xn + (size_t)kA0 * 4096 + fA * 4);
                pa1 = *(const float4*)(xn + (size_t)kA1 * 4096 + fA * 4);
                uint32_t bdst = sbase + BS_OFF + (buf ^ 1) * 16384;
                const float* wn = g_Wscf + (size_t)(c0 + 16) * 256;
#pragma unroll
                for (int i = 0; i < 8; i++) {
                    int g = tid + i * 128;
                    int kB = g >> 6, cB = g & 63;
                    cp_async16(bdst + kB * 1024 + cB * 16, wn + (size_t)kB * 256 + cB * 4);
                }
                CP_COMMIT();
            }
            mma16w(Asd[buf], Bs[buf], acc, tx, ty);
            if (has_next) {
                float* d0 = (float*)&Asd[buf ^ 1][kA0][fA * 4];
                *(float4*)d0       = make_float4(pa0.x, pa0.x, pa0.y, pa0.y);
                *(float4*)(d0 + 4) = make_float4(pa0.z, pa0.z, pa0.w, pa0.w);
                float* d1 = (float*)&Asd[buf ^ 1][kA1][fA * 4];
                *(float4*)d1       = make_float4(pa1.x, pa1.x, pa1.y, pa1.y);
                *(float4*)(d1 + 4) = make_float4(pa1.z, pa1.z, pa1.w, pa1.w);
            }
        }
    }

    // ---------- Phases B/C: (o_r + o_c) @ Wout, K = 256 each -------------
    const int rowA0 = tid >> 2, qA0 = tid & 3;
    const int rowA1 = (tid + 128) >> 2, qA1 = (tid + 128) & 3;
#pragma unroll
    for (int ph = 0; ph < 2; ph++) {
        const float* o_r = ph ? g_o2r : g_o1r;
        const float* o_c = ph ? g_o2c : g_o1c;
        const float* W   = ph ? Wout2 : Wout1;

        float4 sa0, sa1;
        {
            float4 a = *(const float4*)(o_r + (size_t)(s0 + rowA0) * 256 + qA0 * 4);
            float4 c = *(const float4*)(o_c + (size_t)(s0 + rowA0) * 256 + qA0 * 4);
            sa0 = make_float4(a.x + c.x, a.y + c.y, a.z + c.z, a.w + c.w);
            a = *(const float4*)(o_r + (size_t)(s0 + rowA1) * 256 + qA1 * 4);
            c = *(const float4*)(o_c + (size_t)(s0 + rowA1) * 256 + qA1 * 4);
            sa1 = make_float4(a.x + c.x, a.y + c.y, a.z + c.z, a.w + c.w);
        }
        __syncthreads();  // previous phase readers done before overwriting buf
#pragma unroll
        for (int i = 0; i < 8; i++) {
            int g = tid + i * 128;
            int kB = g >> 6, cB = g & 63;
            cp_async16(sbase + BS_OFF + buf * 16384 + kB * 1024 + cB * 16,
                       W + (size_t)kB * 256 + cB * 4);
        }
        CP_COMMIT();
        {
            Asd[buf][qA0 * 4 + 0][rowA0] = dupf(sa0.x);
            Asd[buf][qA0 * 4 + 1][rowA0] = dupf(sa0.y);
            Asd[buf][qA0 * 4 + 2][rowA0] = dupf(sa0.z);
            Asd[buf][qA0 * 4 + 3][rowA0] = dupf(sa0.w);
            Asd[buf][qA1 * 4 + 0][rowA1] = dupf(sa1.x);
            Asd[buf][qA1 * 4 + 1][rowA1] = dupf(sa1.y);
            Asd[buf][qA1 * 4 + 2][rowA1] = dupf(sa1.z);
            Asd[buf][qA1 * 4 + 3][rowA1] = dupf(sa1.w);
        }
        for (int c0 = 0; c0 < 256; c0 += 16, buf ^= 1) {
            CP_WAIT0();
            __syncthreads();
            bool has_next = (c0 + 16 < 256);
            if (has_next) {
                int cn = c0 + 16;
                float4 a = *(const float4*)(o_r + (size_t)(s0 + rowA0) * 256 + cn + qA0 * 4);
                float4 c = *(const float4*)(o_c + (size_t)(s0 + rowA0) * 256 + cn + qA0 * 4);
                sa0 = make_float4(a.x + c.x, a.y + c.y, a.z + c.z, a.w + c.w);
                a = *(const float4*)(o_r + (size_t)(s0 + rowA1) * 256 + cn + qA1 * 4);
                c = *(const float4*)(o_c + (size_t)(s0 + rowA1) * 256 + cn + qA1 * 4);
                sa1 = make_float4(a.x + c.x, a.y + c.y, a.z + c.z, a.w + c.w);
                uint32_t bdst = sbase + BS_OFF + (buf ^ 1) * 16384;
                const float* wn = W + (size_t)cn * 256;
#pragma unroll
                for (int i = 0; i < 8; i++) {
                    int g = tid + i * 128;
                    int kB = g >> 6, cB = g & 63;
                    cp_async16(bdst + kB * 1024 + cB * 16, wn + (size_t)kB * 256 + cB * 4);
                }
                CP_COMMIT();
            }
            mma16w(Asd[buf], Bs[buf], acc, tx, ty);
            if (has_next) {
                Asd[buf ^ 1][qA0 * 4 + 0][rowA0] = dupf(sa0.x);
                Asd[buf ^ 1][qA0 * 4 + 1][rowA0] = dupf(sa0.y);
                Asd[buf ^ 1][qA0 * 4 + 2][rowA0] = dupf(sa0.z);
                Asd[buf ^ 1][qA0 * 4 + 3][rowA0] = dupf(sa0.w);
                Asd[buf ^ 1][qA1 * 4 + 0][rowA1] = dupf(sa1.x);
                Asd[buf ^ 1][qA1 * 4 + 1][rowA1] = dupf(sa1.y);
                Asd[buf ^ 1][qA1 * 4 + 2][rowA1] = dupf(sa1.z);
                Asd[buf ^ 1][qA1 * 4 + 3][rowA1] = dupf(sa1.w);
            }
        }
    }

    // epilogue: bias + x2 residual, store NCHW (cols = q*64 + tx*4 + c)
    float cf[8][16];
#pragma unroll
    for (int i = 0; i < 8; i++)
#pragma unroll
        for (int j = 0; j < 8; j++)
            upk(acc[i][j], cf[i][2 * j], cf[i][2 * j + 1]);

#pragma unroll
    for (int q = 0; q < 4; q++) {
#pragma unroll
        for (int c = 0; c < 4; c++) {
            int o = q * 64 + tx * 4 + c;
            int lcol = q * 4 + c;
            size_t base = ((size_t)(b * 256 + o)) * 4096 + p0 + ty * 8;
            float bt = g_btot[o];
            float4 xa  = *(const float4*)(x2 + base);
            float4 xb4 = *(const float4*)(x2 + base + 4);
            float4 r0, r1;
            r0.x = cf[0][lcol] + bt + xa.x;
            r0.y = cf[1][lcol] + bt + xa.y;
            r0.z = cf[2][lcol] + bt + xa.z;
            r0.w = cf[3][lcol] + bt + xa.w;
            r1.x = cf[4][lcol] + bt + xb4.x;
            r1.y = cf[5][lcol] + bt + xb4.y;
            r1.z = cf[6][lcol] + bt + xb4.z;
            r1.w = cf[7][lcol] + bt + xb4.w;
            *(float4*)(out + base) = r0;
            *(float4*)(out + base + 4) = r1;
        }
    }
}

// ------------------------- launch ---------------------------------------
extern "C" void kernel_launch(void* const* d_in, const int* in_sizes, int n_in,
                              void* d_out, int out_size) {
    (void)in_sizes; (void)n_in; (void)out_size;
    const float* x1      = (const float*)d_in[0];
    const float* x2      = (const float*)d_in[1];
    const float* ln1q_w  = (const float*)d_in[2];
    const float* ln1q_b  = (const float*)d_in[3];
    const float* ln2kv_w = (const float*)d_in[4];
    const float* ln2kv_b = (const float*)d_in[5];
    const float* Wq1     = (const float*)d_in[6];
    const float* Wkv2    = (const float*)d_in[7];
    const float* Wout1   = (const float*)d_in[8];
    const float* bout1   = (const float*)d_in[9];
    const float* ln2q_w  = (const float*)d_in[10];
    const float* ln2q_b  = (const float*)d_in[11];
    const float* ln1kv_w = (const float*)d_in[12];
    const float* ln1kv_b = (const float*)d_in[13];
    const float* Wq2     = (const float*)d_in[14];
    const float* Wkv1    = (const float*)d_in[15];
    const float* Wout2   = (const float*)d_in[16];
    const float* bout2   = (const float*)d_in[17];
    const float* Wsc     = (const float*)d_in[18];
    const float* bn_g    = (const float*)d_in[19];
    const float* bn_b    = (const float*)d_in[20];
    const float* bn_m    = (const float*)d_in[21];
    const float* bn_v    = (const float*)d_in[22];
    float* out = (float*)d_out;

    cudaFuncSetAttribute(proj_both_kernel, cudaFuncAttributeMaxDynamicSharedMemorySize, SMEM_GEMM_BYTES);
    cudaFuncSetAttribute(final_gemm_kernel, cudaFuncAttributeMaxDynamicSharedMemorySize, SMEM_GEMM_BYTES);

    fold_w_kernel<<<1152, 256>>>(Wq1, Wkv1, ln1q_w, ln1kv_w,
                                 Wq2, Wkv2, ln2q_w, ln2kv_w,
                                 Wsc, bn_g, bn_v);
    fold_cols_kernel<<<768, 128>>>(Wq1, Wkv1, ln1q_b, ln1kv_b,
                                   Wq2, Wkv2, ln2q_b, ln2kv_b,
                                   bout1, bout2, bn_g, bn_b, bn_m, bn_v);
    proj_both_kernel<<<dim3(3, 512, 2), 128, SMEM_GEMM_BYTES>>>(x1, x2);
    attn_kernel<<<dim3(64, 32, 4), 64>>>();
    final_gemm_kernel<<<512, 128, SMEM_GEMM_BYTES>>>(x1, x2, Wout1, Wout2, out);
}